// round 1
// baseline (speedup 1.0000x reference)
#include <cuda_runtime.h>
#include <cuda_bf16.h>
#include <math.h>

// Problem constants
#define BATCH 4
#define TT 2048
#define EE 1024
#define HH 16
#define DD 64
#define SEG 512
#define E3 3072

// Scratch (device globals: allocation-free)
static __device__ float g_qkv[(size_t)BATCH * TT * E3];   // [B,T,3E]
static __device__ float g_y[(size_t)BATCH * TT * EE];     // [B,T,E] attention output

// ---------------------------------------------------------------------------
// SGEMM: C[M,N] = A[M,K] @ B[K,N] + bias[N]
// 64x64 block tile, BK=16, 256 threads, 4x4 register tile per thread.
// ---------------------------------------------------------------------------
#define GBM 64
#define GBN 64
#define GBK 16

__global__ __launch_bounds__(256) void sgemm_bias(
    const float* __restrict__ A, const float* __restrict__ B,
    const float* __restrict__ bias, float* __restrict__ C,
    int M, int N, int K)
{
    __shared__ float sA[GBK][GBM];
    __shared__ float sB[GBK][GBN];

    const int tid = threadIdx.x;
    const int tx = tid % 16;
    const int ty = tid / 16;
    const int row0 = blockIdx.y * GBM;
    const int col0 = blockIdx.x * GBN;

    float acc[4][4] = {};

    for (int k0 = 0; k0 < K; k0 += GBK) {
        // Load A tile (64x16) -> sA transposed [k][m]
        #pragma unroll
        for (int i = tid; i < GBM * GBK; i += 256) {
            int r = i / GBK, c = i % GBK;
            sA[c][r] = A[(size_t)(row0 + r) * K + k0 + c];
        }
        // Load B tile (16x64) -> sB [k][n]
        #pragma unroll
        for (int i = tid; i < GBK * GBN; i += 256) {
            int r = i / GBN, c = i % GBN;
            sB[r][c] = B[(size_t)(k0 + r) * N + col0 + c];
        }
        __syncthreads();

        #pragma unroll
        for (int kk = 0; kk < GBK; kk++) {
            float a[4], b[4];
            #pragma unroll
            for (int i = 0; i < 4; i++) a[i] = sA[kk][ty * 4 + i];
            #pragma unroll
            for (int j = 0; j < 4; j++) b[j] = sB[kk][tx * 4 + j];
            #pragma unroll
            for (int i = 0; i < 4; i++)
                #pragma unroll
                for (int j = 0; j < 4; j++)
                    acc[i][j] += a[i] * b[j];
        }
        __syncthreads();
    }

    #pragma unroll
    for (int i = 0; i < 4; i++) {
        int r = row0 + ty * 4 + i;
        #pragma unroll
        for (int j = 0; j < 4; j++) {
            int c = col0 + tx * 4 + j;
            C[(size_t)r * N + c] = acc[i][j] + bias[c];
        }
    }
}

// ---------------------------------------------------------------------------
// Flash attention, fp32. Br=64 query rows per block, Bc=32 kv cols per iter.
// Mask: rows < SEG attend cols < SEG (kv loop stops at SEG);
//       rows >= SEG are causal (kv loop stops at q0+Br; per-element mask only
//       on the diagonal-straddling tiles).
// qkv layout: [B, T, 3E]; q at +0, k at +EE, v at +2*EE (head h -> h*DD).
// ---------------------------------------------------------------------------
#define FBR 64
#define FBC 32

__global__ __launch_bounds__(256) void flash_attn(
    const float* __restrict__ qkv, float* __restrict__ y)
{
    const int qt = blockIdx.x;           // query tile index
    const int bh = blockIdx.y;           // b*H + h
    const int b = bh / HH;
    const int h = bh % HH;
    const int q0 = qt * FBR;

    const float* base = qkv + (size_t)b * TT * E3;

    __shared__ float sQ[FBR][DD];   // 16 KB
    __shared__ float sK[FBC][DD];   //  8 KB
    __shared__ float sV[FBC][DD];   //  8 KB
    __shared__ float sS[FBR][FBC];  //  8 KB
    __shared__ float sm[FBR], sl[FBR], salpha[FBR];

    const int tid = threadIdx.x;
    const int tx = tid % 16;
    const int ty = tid / 16;

    // Load Q tile
    #pragma unroll
    for (int i = tid; i < FBR * DD; i += 256) {
        int r = i / DD, d = i % DD;
        sQ[r][d] = base[(size_t)(q0 + r) * E3 + h * DD + d];
    }
    if (tid < FBR) { sm[tid] = -1e30f; sl[tid] = 0.0f; }

    float o[4][4] = {};
    const int kv_end = (q0 < SEG) ? SEG : (q0 + FBR);
    const float scale = 0.125f;  // 1/sqrt(64)
    __syncthreads();

    for (int kc0 = 0; kc0 < kv_end; kc0 += FBC) {
        // Load K, V tiles
        #pragma unroll
        for (int i = tid; i < FBC * DD; i += 256) {
            int r = i / DD, d = i % DD;
            size_t off = (size_t)(kc0 + r) * E3 + h * DD + d;
            sK[r][d] = base[off + EE];
            sV[r][d] = base[off + 2 * EE];
        }
        __syncthreads();

        // S = Q @ K^T (64x32): thread handles rows 4ty..+3, cols 2tx..+1
        float s[4][2] = {};
        #pragma unroll
        for (int kk = 0; kk < DD; kk++) {
            float a[4], bb[2];
            #pragma unroll
            for (int i = 0; i < 4; i++) a[i] = sQ[ty * 4 + i][kk];
            #pragma unroll
            for (int j = 0; j < 2; j++) bb[j] = sK[tx * 2 + j][kk];
            #pragma unroll
            for (int i = 0; i < 4; i++)
                #pragma unroll
                for (int j = 0; j < 2; j++)
                    s[i][j] += a[i] * bb[j];
        }

        const bool need_mask = (q0 >= SEG) && (kc0 + FBC > q0);
        #pragma unroll
        for (int i = 0; i < 4; i++) {
            int r = q0 + ty * 4 + i;
            #pragma unroll
            for (int j = 0; j < 2; j++) {
                int c = kc0 + tx * 2 + j;
                float val = s[i][j] * scale;
                if (need_mask && c > r) val = -1e30f;
                sS[ty * 4 + i][tx * 2 + j] = val;
            }
        }
        __syncthreads();

        // Online softmax: 4 threads per row, 8 cols each
        {
            const int r = tid / 4;
            const int g = tid % 4;
            float tmax = -1e30f;
            #pragma unroll
            for (int c = g * 8; c < g * 8 + 8; c++) tmax = fmaxf(tmax, sS[r][c]);
            tmax = fmaxf(tmax, __shfl_xor_sync(0xFFFFFFFFu, tmax, 1));
            tmax = fmaxf(tmax, __shfl_xor_sync(0xFFFFFFFFu, tmax, 2));
            const float m_old = sm[r];
            const float m_new = fmaxf(m_old, tmax);
            float lsum = 0.0f;
            #pragma unroll
            for (int c = g * 8; c < g * 8 + 8; c++) {
                float p = __expf(sS[r][c] - m_new);
                sS[r][c] = p;
                lsum += p;
            }
            lsum += __shfl_xor_sync(0xFFFFFFFFu, lsum, 1);
            lsum += __shfl_xor_sync(0xFFFFFFFFu, lsum, 2);
            if (g == 0) {
                float alpha = __expf(m_old - m_new);
                salpha[r] = alpha;
                sm[r] = m_new;
                sl[r] = sl[r] * alpha + lsum;
            }
        }
        __syncthreads();

        // O = O * alpha + P @ V
        #pragma unroll
        for (int i = 0; i < 4; i++) {
            float alpha = salpha[ty * 4 + i];
            #pragma unroll
            for (int j = 0; j < 4; j++) o[i][j] *= alpha;
        }
        #pragma unroll
        for (int kk = 0; kk < FBC; kk++) {
            float p[4], v[4];
            #pragma unroll
            for (int i = 0; i < 4; i++) p[i] = sS[ty * 4 + i][kk];
            #pragma unroll
            for (int j = 0; j < 4; j++) v[j] = sV[kk][tx * 4 + j];
            #pragma unroll
            for (int i = 0; i < 4; i++)
                #pragma unroll
                for (int j = 0; j < 4; j++)
                    o[i][j] += p[i] * v[j];
        }
        __syncthreads();
    }

    // Write y[b, q0+row, h*DD + col] = o / l
    #pragma unroll
    for (int i = 0; i < 4; i++) {
        int r = ty * 4 + i;
        float inv = 1.0f / sl[r];
        #pragma unroll
        for (int j = 0; j < 4; j++) {
            y[((size_t)b * TT + q0 + r) * EE + h * DD + tx * 4 + j] = o[i][j] * inv;
        }
    }
}

// ---------------------------------------------------------------------------
// Launch
// ---------------------------------------------------------------------------
extern "C" void kernel_launch(void* const* d_in, const int* in_sizes, int n_in,
                              void* d_out, int out_size)
{
    const float* x      = (const float*)d_in[0];  // [B,T,E]
    const float* W_qkv  = (const float*)d_in[1];  // [E,3E]
    const float* b_qkv  = (const float*)d_in[2];  // [3E]
    const float* W_proj = (const float*)d_in[3];  // [E,E]
    const float* b_proj = (const float*)d_in[4];  // [E]
    float* out = (float*)d_out;                   // [B,T,E]

    float* qkv;
    float* y;
    cudaGetSymbolAddress((void**)&qkv, g_qkv);
    cudaGetSymbolAddress((void**)&y, g_y);

    const int M = BATCH * TT;  // 8192

    // 1) QKV projection: [8192,1024] @ [1024,3072] + b
    {
        dim3 grid(E3 / GBN, M / GBM);
        sgemm_bias<<<grid, 256>>>(x, W_qkv, b_qkv, qkv, M, E3, EE);
    }

    // 2) Attention
    {
        dim3 grid(TT / FBR, BATCH * HH);
        flash_attn<<<grid, 256>>>(qkv, y);
    }

    // 3) Output projection: [8192,1024] @ [1024,1024] + b
    {
        dim3 grid(EE / GBN, M / GBM);
        sgemm_bias<<<grid, 256>>>(y, W_proj, b_proj, out, M, EE, EE);
    }
}

// round 2
// speedup vs baseline: 3.0397x; 3.0397x over previous
#include <cuda_runtime.h>
#include <cuda_bf16.h>
#include <mma.h>
#include <math.h>

using namespace nvcuda;

// Problem constants
#define BATCH 4
#define TT 2048
#define EE 1024
#define HH 16
#define DD 64
#define SEG 512
#define E3 3072

// Scratch (device globals: allocation-free)
static __device__ float g_qkv[(size_t)BATCH * TT * E3];   // [B,T,3E]
static __device__ float g_y[(size_t)BATCH * TT * EE];     // [B,T,E]

// ---------------------------------------------------------------------------
// TF32 GEMM: C[M,N] = A[M,K] @ B[K,N] + bias[N]
// 128x128 block tile, BK=32, 256 threads (8 warps, 4x2), warp tile 32x64.
// wmma m16n16k8 tf32. Dynamic smem: phase1 A(128x36)+B(32x132), phase2 C(128x132).
// ---------------------------------------------------------------------------
#define GSMEM_BYTES (128 * 132 * 4)

__global__ __launch_bounds__(256) void gemm_tf32(
    const float* __restrict__ A, const float* __restrict__ B,
    const float* __restrict__ bias, float* __restrict__ C,
    int M, int N, int K)
{
    extern __shared__ float smem[];
    float* sA = smem;               // [128][36]
    float* sB = smem + 128 * 36;    // [32][132]

    const int tid = threadIdx.x;
    const int wid = tid >> 5;
    const int wm = wid >> 1;        // 0..3
    const int wn = wid & 1;         // 0..1
    const int row0 = blockIdx.y * 128;
    const int col0 = blockIdx.x * 128;

    wmma::fragment<wmma::accumulator, 16, 16, 8, float> acc[2][4];
    #pragma unroll
    for (int i = 0; i < 2; i++)
        #pragma unroll
        for (int j = 0; j < 4; j++)
            wmma::fill_fragment(acc[i][j], 0.0f);

    for (int k0 = 0; k0 < K; k0 += 32) {
        // Load A tile 128x32 (8 float4 per row)
        #pragma unroll
        for (int idx = tid; idx < 1024; idx += 256) {
            int r = idx >> 3, c4 = idx & 7;
            float4 v = *(const float4*)&A[(size_t)(row0 + r) * K + k0 + c4 * 4];
            v.x = wmma::__float_to_tf32(v.x);
            v.y = wmma::__float_to_tf32(v.y);
            v.z = wmma::__float_to_tf32(v.z);
            v.w = wmma::__float_to_tf32(v.w);
            *(float4*)&sA[r * 36 + c4 * 4] = v;
        }
        // Load B tile 32x128 (32 float4 per row)
        #pragma unroll
        for (int idx = tid; idx < 1024; idx += 256) {
            int r = idx >> 5, c4 = idx & 31;
            float4 v = *(const float4*)&B[(size_t)(k0 + r) * N + col0 + c4 * 4];
            v.x = wmma::__float_to_tf32(v.x);
            v.y = wmma::__float_to_tf32(v.y);
            v.z = wmma::__float_to_tf32(v.z);
            v.w = wmma::__float_to_tf32(v.w);
            *(float4*)&sB[r * 132 + c4 * 4] = v;
        }
        __syncthreads();

        #pragma unroll
        for (int ks = 0; ks < 4; ks++) {
            wmma::fragment<wmma::matrix_a, 16, 16, 8, wmma::precision::tf32, wmma::row_major> af[2];
            wmma::fragment<wmma::matrix_b, 16, 16, 8, wmma::precision::tf32, wmma::row_major> bf[4];
            #pragma unroll
            for (int i = 0; i < 2; i++)
                wmma::load_matrix_sync(af[i], &sA[(wm * 32 + 16 * i) * 36 + ks * 8], 36);
            #pragma unroll
            for (int j = 0; j < 4; j++)
                wmma::load_matrix_sync(bf[j], &sB[(ks * 8) * 132 + wn * 64 + 16 * j], 132);
            #pragma unroll
            for (int i = 0; i < 2; i++)
                #pragma unroll
                for (int j = 0; j < 4; j++)
                    wmma::mma_sync(acc[i][j], af[i], bf[j], acc[i][j]);
        }
        __syncthreads();
    }

    // Epilogue via smem (overlays sA/sB)
    float* sC = smem;  // [128][132]
    #pragma unroll
    for (int i = 0; i < 2; i++)
        #pragma unroll
        for (int j = 0; j < 4; j++)
            wmma::store_matrix_sync(&sC[(wm * 32 + 16 * i) * 132 + wn * 64 + 16 * j],
                                    acc[i][j], 132, wmma::mem_row_major);
    __syncthreads();

    #pragma unroll
    for (int idx = tid; idx < 4096; idx += 256) {
        int r = idx >> 5, c4 = idx & 31;
        float4 v = *(float4*)&sC[r * 132 + c4 * 4];
        float4 bv = *(const float4*)&bias[col0 + c4 * 4];
        v.x += bv.x; v.y += bv.y; v.z += bv.z; v.w += bv.w;
        *(float4*)&C[(size_t)(row0 + r) * N + col0 + c4 * 4] = v;
    }
}

// ---------------------------------------------------------------------------
// Flash attention, tf32 tensor cores. Br=Bc=64. 256 threads (8 warps, 4x2).
// S = Q@K^T via wmma (B col_major = K^T), fp32 online softmax, P@V via wmma.
// O held in per-thread registers; PV result staged through smem.
// ---------------------------------------------------------------------------
#define ALD 68          // padded leading dim for 64-wide tiles
#define ASMEM_BYTES (4 * 64 * ALD * 4)   // sQ, sK, sV, sS

__global__ __launch_bounds__(256) void attn_tf32(
    const float* __restrict__ qkv, float* __restrict__ y)
{
    extern __shared__ float smem[];
    float* sQ = smem;                 // [64][68]
    float* sK = smem + 64 * ALD;
    float* sV = smem + 2 * 64 * ALD;
    float* sS = smem + 3 * 64 * ALD;
    __shared__ float s_m[64], s_l[64], s_a[64];

    const int tid = threadIdx.x;
    const int wid = tid >> 5;
    const int wm = wid >> 1;          // 0..3 (16-row strip)
    const int wn = wid & 1;           // 0..1 (32-col strip)
    const int qt = blockIdx.x;
    const int bh = blockIdx.y;
    const int b = bh / HH;
    const int h = bh % HH;
    const int q0 = qt * 64;

    const float* base = qkv + (size_t)b * TT * E3 + h * DD;

    // Load Q tile (tf32)
    #pragma unroll
    for (int idx = tid; idx < 1024; idx += 256) {
        int r = idx >> 4, c4 = idx & 15;
        float4 v = *(const float4*)&base[(size_t)(q0 + r) * E3 + c4 * 4];
        v.x = wmma::__float_to_tf32(v.x);
        v.y = wmma::__float_to_tf32(v.y);
        v.z = wmma::__float_to_tf32(v.z);
        v.w = wmma::__float_to_tf32(v.w);
        *(float4*)&sQ[r * ALD + c4 * 4] = v;
    }
    if (tid < 64) { s_m[tid] = -1e30f; s_l[tid] = 0.0f; }
    __syncthreads();

    const int rr = tid >> 2;          // softmax/O row (0..63)
    const int g = tid & 3;            // 16-col group
    float O[16] = {};

    const int kv_end = (q0 < SEG) ? SEG : (q0 + 64);
    const bool causal = (q0 >= SEG);

    for (int kc0 = 0; kc0 < kv_end; kc0 += 64) {
        // Load K, V tiles (tf32)
        #pragma unroll
        for (int idx = tid; idx < 1024; idx += 256) {
            int r = idx >> 4, c4 = idx & 15;
            const float* p = &base[(size_t)(kc0 + r) * E3 + c4 * 4];
            float4 kv = *(const float4*)(p + EE);
            float4 vv = *(const float4*)(p + 2 * EE);
            kv.x = wmma::__float_to_tf32(kv.x); kv.y = wmma::__float_to_tf32(kv.y);
            kv.z = wmma::__float_to_tf32(kv.z); kv.w = wmma::__float_to_tf32(kv.w);
            vv.x = wmma::__float_to_tf32(vv.x); vv.y = wmma::__float_to_tf32(vv.y);
            vv.z = wmma::__float_to_tf32(vv.z); vv.w = wmma::__float_to_tf32(vv.w);
            *(float4*)&sK[r * ALD + c4 * 4] = kv;
            *(float4*)&sV[r * ALD + c4 * 4] = vv;
        }
        __syncthreads();

        // S = Q @ K^T : warp computes rows [wm*16,+16), cols [wn*32,+32)
        {
            wmma::fragment<wmma::accumulator, 16, 16, 8, float> sacc[2];
            wmma::fill_fragment(sacc[0], 0.0f);
            wmma::fill_fragment(sacc[1], 0.0f);
            #pragma unroll
            for (int ks = 0; ks < 8; ks++) {
                wmma::fragment<wmma::matrix_a, 16, 16, 8, wmma::precision::tf32, wmma::row_major> af;
                wmma::load_matrix_sync(af, &sQ[(wm * 16) * ALD + ks * 8], ALD);
                #pragma unroll
                for (int j = 0; j < 2; j++) {
                    wmma::fragment<wmma::matrix_b, 16, 16, 8, wmma::precision::tf32, wmma::col_major> bf;
                    wmma::load_matrix_sync(bf, &sK[(wn * 32 + 16 * j) * ALD + ks * 8], ALD);
                    wmma::mma_sync(sacc[j], af, bf, sacc[j]);
                }
            }
            #pragma unroll
            for (int j = 0; j < 2; j++)
                wmma::store_matrix_sync(&sS[(wm * 16) * ALD + wn * 32 + 16 * j],
                                        sacc[j], ALD, wmma::mem_row_major);
        }
        __syncthreads();

        // Online softmax (fp32), 4 threads per row, 16 cols each
        {
            const bool diag = causal && (kc0 == q0);
            float vals[16];
            float tmax = -1e30f;
            #pragma unroll
            for (int j = 0; j < 16; j++) {
                float s = sS[rr * ALD + g * 16 + j] * 0.125f;
                if (diag && (g * 16 + j > rr)) s = -1e30f;
                vals[j] = s;
                tmax = fmaxf(tmax, s);
            }
            tmax = fmaxf(tmax, __shfl_xor_sync(0xFFFFFFFFu, tmax, 1));
            tmax = fmaxf(tmax, __shfl_xor_sync(0xFFFFFFFFu, tmax, 2));
            const float m_old = s_m[rr];
            const float m_new = fmaxf(m_old, tmax);
            float lsum = 0.0f;
            #pragma unroll
            for (int j = 0; j < 16; j++) {
                float p = __expf(vals[j] - m_new);
                lsum += p;
                sS[rr * ALD + g * 16 + j] = wmma::__float_to_tf32(p);
            }
            lsum += __shfl_xor_sync(0xFFFFFFFFu, lsum, 1);
            lsum += __shfl_xor_sync(0xFFFFFFFFu, lsum, 2);
            if (g == 0) {
                float al = __expf(m_old - m_new);
                s_a[rr] = al;
                s_m[rr] = m_new;
                s_l[rr] = s_l[rr] * al + lsum;
            }
        }
        __syncthreads();

        // PV = P @ V : warp computes rows [wm*16,+16), cols [wn*32,+32)
        {
            wmma::fragment<wmma::accumulator, 16, 16, 8, float> oacc[2];
            wmma::fill_fragment(oacc[0], 0.0f);
            wmma::fill_fragment(oacc[1], 0.0f);
            #pragma unroll
            for (int ks = 0; ks < 8; ks++) {
                wmma::fragment<wmma::matrix_a, 16, 16, 8, wmma::precision::tf32, wmma::row_major> af;
                wmma::load_matrix_sync(af, &sS[(wm * 16) * ALD + ks * 8], ALD);
                #pragma unroll
                for (int j = 0; j < 2; j++) {
                    wmma::fragment<wmma::matrix_b, 16, 16, 8, wmma::precision::tf32, wmma::row_major> bf;
                    wmma::load_matrix_sync(bf, &sV[(ks * 8) * ALD + wn * 32 + 16 * j], ALD);
                    wmma::mma_sync(oacc[j], af, bf, oacc[j]);
                }
            }
            __syncthreads();   // all warps done reading P from sS
            #pragma unroll
            for (int j = 0; j < 2; j++)
                wmma::store_matrix_sync(&sS[(wm * 16) * ALD + wn * 32 + 16 * j],
                                        oacc[j], ALD, wmma::mem_row_major);
        }
        __syncthreads();

        // O = O*alpha + PV
        {
            const float al = s_a[rr];
            #pragma unroll
            for (int j = 0; j < 16; j++)
                O[j] = O[j] * al + sS[rr * ALD + g * 16 + j];
        }
        __syncthreads();
    }

    // Write y = O / l
    {
        const float inv = 1.0f / s_l[rr];
        float* outp = y + ((size_t)b * TT + q0 + rr) * EE + h * DD + g * 16;
        #pragma unroll
        for (int j4 = 0; j4 < 4; j4++) {
            float4 v;
            v.x = O[j4 * 4 + 0] * inv;
            v.y = O[j4 * 4 + 1] * inv;
            v.z = O[j4 * 4 + 2] * inv;
            v.w = O[j4 * 4 + 3] * inv;
            *(float4*)&outp[j4 * 4] = v;
        }
    }
}

// ---------------------------------------------------------------------------
// Launch
// ---------------------------------------------------------------------------
extern "C" void kernel_launch(void* const* d_in, const int* in_sizes, int n_in,
                              void* d_out, int out_size)
{
    const float* x      = (const float*)d_in[0];  // [B,T,E]
    const float* W_qkv  = (const float*)d_in[1];  // [E,3E]
    const float* b_qkv  = (const float*)d_in[2];  // [3E]
    const float* W_proj = (const float*)d_in[3];  // [E,E]
    const float* b_proj = (const float*)d_in[4];  // [E]
    float* out = (float*)d_out;                   // [B,T,E]

    float* qkv;
    float* y;
    cudaGetSymbolAddress((void**)&qkv, g_qkv);
    cudaGetSymbolAddress((void**)&y, g_y);

    cudaFuncSetAttribute(gemm_tf32, cudaFuncAttributeMaxDynamicSharedMemorySize, GSMEM_BYTES);
    cudaFuncSetAttribute(attn_tf32, cudaFuncAttributeMaxDynamicSharedMemorySize, ASMEM_BYTES);

    const int M = BATCH * TT;  // 8192

    // 1) QKV projection: [8192,1024] @ [1024,3072] + b
    {
        dim3 grid(E3 / 128, M / 128);
        gemm_tf32<<<grid, 256, GSMEM_BYTES>>>(x, W_qkv, b_qkv, qkv, M, E3, EE);
    }

    // 2) Attention
    {
        dim3 grid(TT / 64, BATCH * HH);
        attn_tf32<<<grid, 256, ASMEM_BYTES>>>(qkv, y);
    }

    // 3) Output projection: [8192,1024] @ [1024,1024] + b
    {
        dim3 grid(EE / 128, M / 128);
        gemm_tf32<<<grid, 256, GSMEM_BYTES>>>(y, W_proj, b_proj, out, M, EE, EE);
    }
}

// round 3
// speedup vs baseline: 3.7999x; 1.2501x over previous
#include <cuda_runtime.h>
#include <cuda_bf16.h>
#include <mma.h>
#include <math.h>
#include <stdint.h>

using namespace nvcuda;

// Problem constants
#define BATCH 4
#define TT 2048
#define EE 1024
#define HH 16
#define DD 64
#define SEG 512
#define E3 3072

// Scratch (device globals: allocation-free)
static __device__ float g_qkv[(size_t)BATCH * TT * E3];   // [B,T,3E]
static __device__ float g_y[(size_t)BATCH * TT * EE];     // [B,T,E]

// ---------------------------------------------------------------------------
// cp.async helpers
// ---------------------------------------------------------------------------
__device__ __forceinline__ void cp_async16(uint32_t smem_dst, const void* gsrc) {
    asm volatile("cp.async.cg.shared.global [%0], [%1], 16;\n" :: "r"(smem_dst), "l"(gsrc));
}
__device__ __forceinline__ void cp_commit() {
    asm volatile("cp.async.commit_group;\n" ::: "memory");
}
template <int N>
__device__ __forceinline__ void cp_wait() {
    asm volatile("cp.async.wait_group %0;\n" :: "n"(N) : "memory");
}

// ---------------------------------------------------------------------------
// TF32 GEMM: C[M,N] = A[M,K] @ B[K,N] + bias[N]
// 128x128 block tile, BK=32, 2-stage cp.async pipeline, 256 threads (8 warps),
// warp tile 32x64, wmma m16n16k8 tf32 with in-fragment tf32 rounding.
// smem per stage: A[128][36] + B[32][132] = 8832 floats. 2 stages = 70.7 KB.
// ---------------------------------------------------------------------------
#define G_STAGE 8832
#define GSMEM_BYTES (2 * G_STAGE * 4)

__global__ __launch_bounds__(256) void gemm_tf32(
    const float* __restrict__ A, const float* __restrict__ B,
    const float* __restrict__ bias, float* __restrict__ C,
    int M, int N, int K)
{
    extern __shared__ float smem[];
    const uint32_t smem_base = (uint32_t)__cvta_generic_to_shared(smem);

    const int tid = threadIdx.x;
    const int wid = tid >> 5;
    const int wm = wid >> 1;        // 0..3
    const int wn = wid & 1;         // 0..1
    const int row0 = blockIdx.y * 128;
    const int col0 = blockIdx.x * 128;

    const int nsteps = K >> 5;      // K/32

    // per-thread load coordinates
    const int a_r = tid >> 1;               // 0..127 (2 float4 per row -> 4 loads)
    const int a_c4 = (tid & 1) * 4;         // 0 or 4 -> covers c4 0..7 via +0/+... 
    const int b_r = tid >> 3;               // 0..31
    const int b_c4 = tid & 7;               // 0..7 -> covers c4 via *4 stride

    auto stage_load = [&](int s, int k0) {
        uint32_t sa = smem_base + (uint32_t)(s * G_STAGE) * 4u;
        uint32_t sb = sa + 4608u * 4u;
        // A tile 128x32: 1024 float4, 256 threads -> 4 each
        #pragma unroll
        for (int i = 0; i < 4; i++) {
            int idx = tid + i * 256;
            int r = idx >> 3, c4 = idx & 7;
            cp_async16(sa + (uint32_t)(r * 36 + c4 * 4) * 4u,
                       &A[(size_t)(row0 + r) * K + k0 + c4 * 4]);
        }
        // B tile 32x128: 1024 float4
        #pragma unroll
        for (int i = 0; i < 4; i++) {
            int idx = tid + i * 256;
            int r = idx >> 5, c4 = idx & 31;
            cp_async16(sb + (uint32_t)(r * 132 + c4 * 4) * 4u,
                       &B[(size_t)(k0 + r) * N + col0 + c4 * 4]);
        }
    };

    wmma::fragment<wmma::accumulator, 16, 16, 8, float> acc[2][4];
    #pragma unroll
    for (int i = 0; i < 2; i++)
        #pragma unroll
        for (int j = 0; j < 4; j++)
            wmma::fill_fragment(acc[i][j], 0.0f);

    // prologue
    stage_load(0, 0); cp_commit();
    stage_load(1, 32); cp_commit();

    for (int step = 0; step < nsteps; step++) {
        cp_wait<1>();
        __syncthreads();
        const int cur = step & 1;
        float* sA = smem + cur * G_STAGE;
        float* sB = sA + 4608;

        #pragma unroll
        for (int ks = 0; ks < 4; ks++) {
            wmma::fragment<wmma::matrix_a, 16, 16, 8, wmma::precision::tf32, wmma::row_major> af[2];
            wmma::fragment<wmma::matrix_b, 16, 16, 8, wmma::precision::tf32, wmma::row_major> bf[4];
            #pragma unroll
            for (int i = 0; i < 2; i++) {
                wmma::load_matrix_sync(af[i], &sA[(wm * 32 + 16 * i) * 36 + ks * 8], 36);
                #pragma unroll
                for (int e = 0; e < af[i].num_elements; e++)
                    af[i].x[e] = wmma::__float_to_tf32(af[i].x[e]);
            }
            #pragma unroll
            for (int j = 0; j < 4; j++) {
                wmma::load_matrix_sync(bf[j], &sB[(ks * 8) * 132 + wn * 64 + 16 * j], 132);
                #pragma unroll
                for (int e = 0; e < bf[j].num_elements; e++)
                    bf[j].x[e] = wmma::__float_to_tf32(bf[j].x[e]);
            }
            #pragma unroll
            for (int i = 0; i < 2; i++)
                #pragma unroll
                for (int j = 0; j < 4; j++)
                    wmma::mma_sync(acc[i][j], af[i], bf[j], acc[i][j]);
        }
        __syncthreads();
        if (step + 2 < nsteps) stage_load(cur, (step + 2) * 32);
        cp_commit();
    }

    // Epilogue via smem overlay
    float* sC = smem;  // [128][132]
    #pragma unroll
    for (int i = 0; i < 2; i++)
        #pragma unroll
        for (int j = 0; j < 4; j++)
            wmma::store_matrix_sync(&sC[(wm * 32 + 16 * i) * 132 + wn * 64 + 16 * j],
                                    acc[i][j], 132, wmma::mem_row_major);
    __syncthreads();

    #pragma unroll
    for (int idx = tid; idx < 4096; idx += 256) {
        int r = idx >> 5, c4 = idx & 31;
        float4 v = *(float4*)&sC[r * 132 + c4 * 4];
        float4 bv = *(const float4*)&bias[col0 + c4 * 4];
        v.x += bv.x; v.y += bv.y; v.z += bv.z; v.w += bv.w;
        *(float4*)&C[(size_t)(row0 + r) * N + col0 + c4 * 4] = v;
    }
}

// ---------------------------------------------------------------------------
// Flash attention v2-style, mma.sync.m16n8k8.tf32 with register-resident
// S and O. Br=128 (warp owns 16 rows), Bc=64, 8 warps, 256 threads.
// smem: sK[64][68], sV[64][68], sP[128][68] (also used to stage Q once).
// ---------------------------------------------------------------------------
#define ALD 68
#define ASMEM_FLOATS ((64 + 64 + 128) * ALD)
#define ASMEM_BYTES (ASMEM_FLOATS * 4)

__device__ __forceinline__ void mma_tf32_16x8x8(
    float c[4], const uint32_t a[4], const uint32_t b0, const uint32_t b1)
{
    asm volatile(
        "mma.sync.aligned.m16n8k8.row.col.f32.tf32.tf32.f32 "
        "{%0,%1,%2,%3}, {%4,%5,%6,%7}, {%8,%9}, {%0,%1,%2,%3};"
        : "+f"(c[0]), "+f"(c[1]), "+f"(c[2]), "+f"(c[3])
        : "r"(a[0]), "r"(a[1]), "r"(a[2]), "r"(a[3]), "r"(b0), "r"(b1));
}

__device__ __forceinline__ float to_tf32(float x) {
    float r;
    asm("cvt.rna.tf32.f32 %0, %1;\n" : "=f"(r) : "f"(x));
    return r;
}

__global__ __launch_bounds__(256) void attn_tf32(
    const float* __restrict__ qkv, float* __restrict__ y)
{
    extern __shared__ float smem[];
    float* sK = smem;                       // [64][68]
    float* sV = smem + 64 * ALD;            // [64][68]
    float* sP = smem + 128 * ALD;           // [128][68] (Q staging, then P)

    const int tid = threadIdx.x;
    const int w = tid >> 5;
    const int lane = tid & 31;
    const int g = lane >> 2;                // group row 0..7
    const int t = lane & 3;                 // thread-in-group 0..3

    const int q0 = blockIdx.x * 128;
    const int bh = blockIdx.y;
    const int b = bh / HH;
    const int h = bh % HH;

    const float* base = qkv + (size_t)b * TT * E3 + h * DD;

    // ---- Stage Q tile (128x64) into sP, converted to tf32 ----
    #pragma unroll
    for (int i = 0; i < 8; i++) {
        int idx = tid + i * 256;
        int r = idx >> 4, c4 = idx & 15;
        float4 v = *(const float4*)&base[(size_t)(q0 + r) * E3 + c4 * 4];
        v.x = to_tf32(v.x); v.y = to_tf32(v.y); v.z = to_tf32(v.z); v.w = to_tf32(v.w);
        *(float4*)&sP[r * ALD + c4 * 4] = v;
    }
    __syncthreads();

    // ---- Load Q a-frags into registers: rows w*16+g, w*16+g+8 ----
    uint32_t aQ[8][4];
    {
        const int r0 = w * 16 + g;
        #pragma unroll
        for (int ks = 0; ks < 8; ks++) {
            aQ[ks][0] = __float_as_uint(sP[r0 * ALD + ks * 8 + t]);
            aQ[ks][1] = __float_as_uint(sP[(r0 + 8) * ALD + ks * 8 + t]);
            aQ[ks][2] = __float_as_uint(sP[r0 * ALD + ks * 8 + t + 4]);
            aQ[ks][3] = __float_as_uint(sP[(r0 + 8) * ALD + ks * 8 + t + 4]);
        }
    }

    float O[8][4];
    #pragma unroll
    for (int j = 0; j < 8; j++) { O[j][0] = O[j][1] = O[j][2] = O[j][3] = 0.0f; }
    float m0 = -1e30f, m1 = -1e30f, l0 = 0.0f, l1 = 0.0f;

    const bool causal = (q0 >= SEG);
    const int kv_end = causal ? (q0 + 128) : SEG;
    const int row0g = q0 + w * 16 + g;       // global row of c0/c1
    const int rowmax = q0 + w * 16 + 15;     // max row this warp owns
    const float scale = 0.125f;              // 1/sqrt(64)

    for (int kc0 = 0; kc0 < kv_end; kc0 += 64) {
        __syncthreads();   // everyone done with prev sK/sV (and Q regs loaded)
        // ---- Load K, V tiles (64x64), converted ----
        #pragma unroll
        for (int i = 0; i < 4; i++) {
            int idx = tid + i * 256;
            int r = idx >> 4, c4 = idx & 15;
            const float* p = &base[(size_t)(kc0 + r) * E3 + c4 * 4];
            float4 kv = *(const float4*)(p + EE);
            float4 vv = *(const float4*)(p + 2 * EE);
            kv.x = to_tf32(kv.x); kv.y = to_tf32(kv.y);
            kv.z = to_tf32(kv.z); kv.w = to_tf32(kv.w);
            vv.x = to_tf32(vv.x); vv.y = to_tf32(vv.y);
            vv.z = to_tf32(vv.z); vv.w = to_tf32(vv.w);
            *(float4*)&sK[r * ALD + c4 * 4] = kv;
            *(float4*)&sV[r * ALD + c4 * 4] = vv;
        }
        __syncthreads();

        const bool active = !(causal && kc0 > rowmax);
        if (active) {
            // ---- S = Q @ K^T : warp rows [w*16, +16), cols [0,64) ----
            float s[8][4];
            #pragma unroll
            for (int j = 0; j < 8; j++) {
                s[j][0] = s[j][1] = s[j][2] = s[j][3] = 0.0f;
                #pragma unroll
                for (int ks = 0; ks < 8; ks++) {
                    uint32_t b0 = __float_as_uint(sK[(j * 8 + g) * ALD + ks * 8 + t]);
                    uint32_t b1 = __float_as_uint(sK[(j * 8 + g) * ALD + ks * 8 + t + 4]);
                    mma_tf32_16x8x8(s[j], aQ[ks], b0, b1);
                }
            }

            // ---- scale + mask + online softmax (registers + quad shuffles) ----
            const bool maskT = causal && (kc0 + 63 > q0 + w * 16);
            float t0 = -1e30f, t1 = -1e30f;
            #pragma unroll
            for (int j = 0; j < 8; j++) {
                int c = kc0 + j * 8 + 2 * t;
                #pragma unroll
                for (int e = 0; e < 4; e++) {
                    float v = s[j][e] * scale;
                    int col = c + (e & 1);
                    int row = row0g + ((e >> 1) << 3);
                    if (maskT && col > row) v = -1e30f;
                    s[j][e] = v;
                }
                t0 = fmaxf(t0, fmaxf(s[j][0], s[j][1]));
                t1 = fmaxf(t1, fmaxf(s[j][2], s[j][3]));
            }
            t0 = fmaxf(t0, __shfl_xor_sync(0xFFFFFFFFu, t0, 1));
            t0 = fmaxf(t0, __shfl_xor_sync(0xFFFFFFFFu, t0, 2));
            t1 = fmaxf(t1, __shfl_xor_sync(0xFFFFFFFFu, t1, 1));
            t1 = fmaxf(t1, __shfl_xor_sync(0xFFFFFFFFu, t1, 2));

            const float mn0 = fmaxf(m0, t0);
            const float mn1 = fmaxf(m1, t1);
            const float alpha0 = __expf(m0 - mn0);
            const float alpha1 = __expf(m1 - mn1);
            m0 = mn0; m1 = mn1;

            float sum0 = 0.0f, sum1 = 0.0f;
            const int pr0 = w * 16 + g;
            #pragma unroll
            for (int j = 0; j < 8; j++) {
                float p0 = __expf(s[j][0] - mn0);
                float p1 = __expf(s[j][1] - mn0);
                float p2 = __expf(s[j][2] - mn1);
                float p3 = __expf(s[j][3] - mn1);
                sum0 += p0 + p1;
                sum1 += p2 + p3;
                // write P (tf32-rounded) to warp-private sP region
                sP[pr0 * ALD + j * 8 + 2 * t]       = to_tf32(p0);
                sP[pr0 * ALD + j * 8 + 2 * t + 1]   = to_tf32(p1);
                sP[(pr0 + 8) * ALD + j * 8 + 2 * t]     = to_tf32(p2);
                sP[(pr0 + 8) * ALD + j * 8 + 2 * t + 1] = to_tf32(p3);
            }
            sum0 += __shfl_xor_sync(0xFFFFFFFFu, sum0, 1);
            sum0 += __shfl_xor_sync(0xFFFFFFFFu, sum0, 2);
            sum1 += __shfl_xor_sync(0xFFFFFFFFu, sum1, 1);
            sum1 += __shfl_xor_sync(0xFFFFFFFFu, sum1, 2);
            l0 = l0 * alpha0 + sum0;
            l1 = l1 * alpha1 + sum1;

            // rescale O
            #pragma unroll
            for (int j = 0; j < 8; j++) {
                O[j][0] *= alpha0; O[j][1] *= alpha0;
                O[j][2] *= alpha1; O[j][3] *= alpha1;
            }
            __syncwarp();

            // ---- O += P @ V ----
            #pragma unroll
            for (int ks = 0; ks < 8; ks++) {
                uint32_t aP[4];
                aP[0] = __float_as_uint(sP[pr0 * ALD + ks * 8 + t]);
                aP[1] = __float_as_uint(sP[(pr0 + 8) * ALD + ks * 8 + t]);
                aP[2] = __float_as_uint(sP[pr0 * ALD + ks * 8 + t + 4]);
                aP[3] = __float_as_uint(sP[(pr0 + 8) * ALD + ks * 8 + t + 4]);
                #pragma unroll
                for (int j = 0; j < 8; j++) {
                    uint32_t b0 = __float_as_uint(sV[(ks * 8 + t) * ALD + j * 8 + g]);
                    uint32_t b1 = __float_as_uint(sV[(ks * 8 + t + 4) * ALD + j * 8 + g]);
                    mma_tf32_16x8x8(O[j], aP, b0, b1);
                }
            }
        }
    }

    // ---- Write y = O / l ----
    {
        const float inv0 = 1.0f / l0;
        const float inv1 = 1.0f / l1;
        const int gr0 = q0 + w * 16 + g;
        float* y0 = y + ((size_t)b * TT + gr0) * EE + h * DD;
        float* y1 = y0 + 8 * EE;
        #pragma unroll
        for (int j = 0; j < 8; j++) {
            float2 v0 = { O[j][0] * inv0, O[j][1] * inv0 };
            float2 v1 = { O[j][2] * inv1, O[j][3] * inv1 };
            *(float2*)&y0[j * 8 + 2 * t] = v0;
            *(float2*)&y1[j * 8 + 2 * t] = v1;
        }
    }
}

// ---------------------------------------------------------------------------
// Launch
// ---------------------------------------------------------------------------
extern "C" void kernel_launch(void* const* d_in, const int* in_sizes, int n_in,
                              void* d_out, int out_size)
{
    const float* x      = (const float*)d_in[0];  // [B,T,E]
    const float* W_qkv  = (const float*)d_in[1];  // [E,3E]
    const float* b_qkv  = (const float*)d_in[2];  // [3E]
    const float* W_proj = (const float*)d_in[3];  // [E,E]
    const float* b_proj = (const float*)d_in[4];  // [E]
    float* out = (float*)d_out;                   // [B,T,E]

    float* qkv;
    float* y;
    cudaGetSymbolAddress((void**)&qkv, g_qkv);
    cudaGetSymbolAddress((void**)&y, g_y);

    cudaFuncSetAttribute(gemm_tf32, cudaFuncAttributeMaxDynamicSharedMemorySize, GSMEM_BYTES);
    cudaFuncSetAttribute(attn_tf32, cudaFuncAttributeMaxDynamicSharedMemorySize, ASMEM_BYTES);

    const int M = BATCH * TT;  // 8192

    // 1) QKV projection: [8192,1024] @ [1024,3072] + b
    {
        dim3 grid(E3 / 128, M / 128);
        gemm_tf32<<<grid, 256, GSMEM_BYTES>>>(x, W_qkv, b_qkv, qkv, M, E3, EE);
    }

    // 2) Attention: Br=128 -> 16 q-tiles per (b,h)
    {
        dim3 grid(TT / 128, BATCH * HH);
        attn_tf32<<<grid, 256, ASMEM_BYTES>>>(qkv, y);
    }

    // 3) Output projection: [8192,1024] @ [1024,1024] + b
    {
        dim3 grid(EE / 128, M / 128);
        gemm_tf32<<<grid, 256, GSMEM_BYTES>>>(y, W_proj, b_proj, out, M, EE, EE);
    }
}

// round 4
// speedup vs baseline: 3.8646x; 1.0170x over previous
#include <cuda_runtime.h>
#include <cuda_bf16.h>
#include <mma.h>
#include <math.h>
#include <stdint.h>

using namespace nvcuda;

// Problem constants
#define BATCH 4
#define TT 2048
#define EE 1024
#define HH 16
#define DD 64
#define SEG 512
#define E3 3072

// Scratch (device globals: allocation-free)
static __device__ float g_qkv[(size_t)BATCH * TT * E3];   // [B,T,3E] (tf32-rounded)
static __device__ float g_y[(size_t)BATCH * TT * EE];     // [B,T,E]  (tf32-rounded)
static __device__ float g_xc[(size_t)BATCH * TT * EE];    // x, tf32-rounded
static __device__ float g_wq[(size_t)EE * E3];            // W_qkv, tf32-rounded
static __device__ float g_wp[(size_t)EE * EE];            // W_proj, tf32-rounded

// ---------------------------------------------------------------------------
// helpers
// ---------------------------------------------------------------------------
__device__ __forceinline__ void cp_async16(uint32_t smem_dst, const void* gsrc) {
    asm volatile("cp.async.cg.shared.global [%0], [%1], 16;\n" :: "r"(smem_dst), "l"(gsrc));
}
__device__ __forceinline__ void cp_commit() {
    asm volatile("cp.async.commit_group;\n" ::: "memory");
}
template <int N>
__device__ __forceinline__ void cp_wait() {
    asm volatile("cp.async.wait_group %0;\n" :: "n"(N) : "memory");
}
__device__ __forceinline__ float to_tf32(float x) {
    float r;
    asm("cvt.rna.tf32.f32 %0, %1;\n" : "=f"(r) : "f"(x));
    return r;
}

// Elementwise tf32 rounding: out[i] = tf32(in[i]), n multiple of 1024
__global__ __launch_bounds__(256) void cvt_tf32_kernel(
    const float* __restrict__ in, float* __restrict__ out, int n4)
{
    int i = blockIdx.x * 256 + threadIdx.x;
    if (i < n4) {
        float4 v = ((const float4*)in)[i];
        v.x = to_tf32(v.x); v.y = to_tf32(v.y);
        v.z = to_tf32(v.z); v.w = to_tf32(v.w);
        ((float4*)out)[i] = v;
    }
}

// ---------------------------------------------------------------------------
// TF32 GEMM: C[M,N] = A[M,K] @ B[K,N] + bias[N]   (A,B pre-rounded to tf32)
// 128x128 block tile, BK=32, 2-stage cp.async pipeline, 256 threads (8 warps),
// warp tile 32x64, wmma m16n16k8 tf32. No conversions in mainloop.
// ROUND_OUT: round C to tf32 in epilogue (for qkv, consumed by tf32 attention)
// ---------------------------------------------------------------------------
#define G_STAGE 8832
#define GSMEM_BYTES (2 * G_STAGE * 4)

template <bool ROUND_OUT>
__global__ __launch_bounds__(256, 2) void gemm_tf32(
    const float* __restrict__ A, const float* __restrict__ B,
    const float* __restrict__ bias, float* __restrict__ C,
    int M, int N, int K)
{
    extern __shared__ float smem[];
    const uint32_t smem_base = (uint32_t)__cvta_generic_to_shared(smem);

    const int tid = threadIdx.x;
    const int wid = tid >> 5;
    const int wm = wid >> 1;        // 0..3
    const int wn = wid & 1;         // 0..1
    const int row0 = blockIdx.y * 128;
    const int col0 = blockIdx.x * 128;

    const int nsteps = K >> 5;      // K/32

    auto stage_load = [&](int s, int k0) {
        uint32_t sa = smem_base + (uint32_t)(s * G_STAGE) * 4u;
        uint32_t sb = sa + 4608u * 4u;
        #pragma unroll
        for (int i = 0; i < 4; i++) {
            int idx = tid + i * 256;
            int r = idx >> 3, c4 = idx & 7;
            cp_async16(sa + (uint32_t)(r * 36 + c4 * 4) * 4u,
                       &A[(size_t)(row0 + r) * K + k0 + c4 * 4]);
        }
        #pragma unroll
        for (int i = 0; i < 4; i++) {
            int idx = tid + i * 256;
            int r = idx >> 5, c4 = idx & 31;
            cp_async16(sb + (uint32_t)(r * 132 + c4 * 4) * 4u,
                       &B[(size_t)(k0 + r) * N + col0 + c4 * 4]);
        }
    };

    wmma::fragment<wmma::accumulator, 16, 16, 8, float> acc[2][4];
    #pragma unroll
    for (int i = 0; i < 2; i++)
        #pragma unroll
        for (int j = 0; j < 4; j++)
            wmma::fill_fragment(acc[i][j], 0.0f);

    stage_load(0, 0); cp_commit();
    stage_load(1, 32); cp_commit();

    for (int step = 0; step < nsteps; step++) {
        cp_wait<1>();
        __syncthreads();
        const int cur = step & 1;
        float* sA = smem + cur * G_STAGE;
        float* sB = sA + 4608;

        #pragma unroll
        for (int ks = 0; ks < 4; ks++) {
            wmma::fragment<wmma::matrix_a, 16, 16, 8, wmma::precision::tf32, wmma::row_major> af[2];
            wmma::fragment<wmma::matrix_b, 16, 16, 8, wmma::precision::tf32, wmma::row_major> bf[4];
            #pragma unroll
            for (int i = 0; i < 2; i++)
                wmma::load_matrix_sync(af[i], &sA[(wm * 32 + 16 * i) * 36 + ks * 8], 36);
            #pragma unroll
            for (int j = 0; j < 4; j++)
                wmma::load_matrix_sync(bf[j], &sB[(ks * 8) * 132 + wn * 64 + 16 * j], 132);
            #pragma unroll
            for (int i = 0; i < 2; i++)
                #pragma unroll
                for (int j = 0; j < 4; j++)
                    wmma::mma_sync(acc[i][j], af[i], bf[j], acc[i][j]);
        }
        __syncthreads();
        if (step + 2 < nsteps) stage_load(cur, (step + 2) * 32);
        cp_commit();
    }

    // Epilogue via smem overlay
    float* sC = smem;  // [128][132]
    #pragma unroll
    for (int i = 0; i < 2; i++)
        #pragma unroll
        for (int j = 0; j < 4; j++)
            wmma::store_matrix_sync(&sC[(wm * 32 + 16 * i) * 132 + wn * 64 + 16 * j],
                                    acc[i][j], 132, wmma::mem_row_major);
    __syncthreads();

    #pragma unroll
    for (int idx = tid; idx < 4096; idx += 256) {
        int r = idx >> 5, c4 = idx & 31;
        float4 v = *(float4*)&sC[r * 132 + c4 * 4];
        float4 bv = *(const float4*)&bias[col0 + c4 * 4];
        v.x += bv.x; v.y += bv.y; v.z += bv.z; v.w += bv.w;
        if (ROUND_OUT) {
            v.x = to_tf32(v.x); v.y = to_tf32(v.y);
            v.z = to_tf32(v.z); v.w = to_tf32(v.w);
        }
        *(float4*)&C[(size_t)(row0 + r) * N + col0 + c4 * 4] = v;
    }
}

// ---------------------------------------------------------------------------
// Flash attention v2-style, mma.sync.m16n8k8.tf32 with register-resident
// S and O. Br=128 (warp owns 16 rows), Bc=64, 8 warps, 256 threads.
// qkv pre-rounded to tf32 by GEMM1 epilogue -> no cvt in load paths.
// smem: sK[64][68], sV[64][68], sP[128][68] (Q staging, then P).
// ---------------------------------------------------------------------------
#define ALD 68
#define ASMEM_BYTES (((64 + 64 + 128) * ALD) * 4)

__device__ __forceinline__ void mma_tf32_16x8x8(
    float c[4], const uint32_t a[4], const uint32_t b0, const uint32_t b1)
{
    asm volatile(
        "mma.sync.aligned.m16n8k8.row.col.f32.tf32.tf32.f32 "
        "{%0,%1,%2,%3}, {%4,%5,%6,%7}, {%8,%9}, {%0,%1,%2,%3};"
        : "+f"(c[0]), "+f"(c[1]), "+f"(c[2]), "+f"(c[3])
        : "r"(a[0]), "r"(a[1]), "r"(a[2]), "r"(a[3]), "r"(b0), "r"(b1));
}

__global__ __launch_bounds__(256) void attn_tf32(
    const float* __restrict__ qkv, float* __restrict__ y)
{
    extern __shared__ float smem[];
    float* sK = smem;                       // [64][68]
    float* sV = smem + 64 * ALD;            // [64][68]
    float* sP = smem + 128 * ALD;           // [128][68]
    const uint32_t smem_u = (uint32_t)__cvta_generic_to_shared(smem);
    const uint32_t sK_u = smem_u;
    const uint32_t sV_u = smem_u + 64 * ALD * 4;
    const uint32_t sP_u = smem_u + 128 * ALD * 4;

    const int tid = threadIdx.x;
    const int w = tid >> 5;
    const int lane = tid & 31;
    const int g = lane >> 2;
    const int t = lane & 3;

    const int q0 = blockIdx.x * 128;
    const int bh = blockIdx.y;
    const int b = bh / HH;
    const int h = bh % HH;

    const float* base = qkv + (size_t)b * TT * E3 + h * DD;

    // ---- Stage Q tile (128x64) into sP via cp.async ----
    #pragma unroll
    for (int i = 0; i < 8; i++) {
        int idx = tid + i * 256;
        int r = idx >> 4, c4 = idx & 15;
        cp_async16(sP_u + (uint32_t)(r * ALD + c4 * 4) * 4u,
                   &base[(size_t)(q0 + r) * E3 + c4 * 4]);
    }
    cp_commit();
    cp_wait<0>();
    __syncthreads();

    // ---- Load Q a-frags into registers ----
    uint32_t aQ[8][4];
    {
        const int r0 = w * 16 + g;
        #pragma unroll
        for (int ks = 0; ks < 8; ks++) {
            aQ[ks][0] = __float_as_uint(sP[r0 * ALD + ks * 8 + t]);
            aQ[ks][1] = __float_as_uint(sP[(r0 + 8) * ALD + ks * 8 + t]);
            aQ[ks][2] = __float_as_uint(sP[r0 * ALD + ks * 8 + t + 4]);
            aQ[ks][3] = __float_as_uint(sP[(r0 + 8) * ALD + ks * 8 + t + 4]);
        }
    }

    float O[8][4];
    #pragma unroll
    for (int j = 0; j < 8; j++) { O[j][0] = O[j][1] = O[j][2] = O[j][3] = 0.0f; }
    float m0 = -1e30f, m1 = -1e30f, l0 = 0.0f, l1 = 0.0f;

    const bool causal = (q0 >= SEG);
    const int kv_end = causal ? (q0 + 128) : SEG;
    const int row0g = q0 + w * 16 + g;
    const int rowmax = q0 + w * 16 + 15;
    const float scale = 0.125f;

    for (int kc0 = 0; kc0 < kv_end; kc0 += 64) {
        __syncthreads();
        // ---- K, V tiles via cp.async ----
        #pragma unroll
        for (int i = 0; i < 4; i++) {
            int idx = tid + i * 256;
            int r = idx >> 4, c4 = idx & 15;
            const float* p = &base[(size_t)(kc0 + r) * E3 + c4 * 4];
            uint32_t soff = (uint32_t)(r * ALD + c4 * 4) * 4u;
            cp_async16(sK_u + soff, p + EE);
            cp_async16(sV_u + soff, p + 2 * EE);
        }
        cp_commit();
        cp_wait<0>();
        __syncthreads();

        const bool active = !(causal && kc0 > rowmax);
        if (active) {
            // ---- S = Q @ K^T ----
            float s[8][4];
            #pragma unroll
            for (int j = 0; j < 8; j++) {
                s[j][0] = s[j][1] = s[j][2] = s[j][3] = 0.0f;
                #pragma unroll
                for (int ks = 0; ks < 8; ks++) {
                    uint32_t b0 = __float_as_uint(sK[(j * 8 + g) * ALD + ks * 8 + t]);
                    uint32_t b1 = __float_as_uint(sK[(j * 8 + g) * ALD + ks * 8 + t + 4]);
                    mma_tf32_16x8x8(s[j], aQ[ks], b0, b1);
                }
            }

            // ---- scale + mask + online softmax ----
            const bool maskT = causal && (kc0 + 63 > q0 + w * 16);
            float t0 = -1e30f, t1 = -1e30f;
            #pragma unroll
            for (int j = 0; j < 8; j++) {
                int c = kc0 + j * 8 + 2 * t;
                #pragma unroll
                for (int e = 0; e < 4; e++) {
                    float v = s[j][e] * scale;
                    int col = c + (e & 1);
                    int row = row0g + ((e >> 1) << 3);
                    if (maskT && col > row) v = -1e30f;
                    s[j][e] = v;
                }
                t0 = fmaxf(t0, fmaxf(s[j][0], s[j][1]));
                t1 = fmaxf(t1, fmaxf(s[j][2], s[j][3]));
            }
            t0 = fmaxf(t0, __shfl_xor_sync(0xFFFFFFFFu, t0, 1));
            t0 = fmaxf(t0, __shfl_xor_sync(0xFFFFFFFFu, t0, 2));
            t1 = fmaxf(t1, __shfl_xor_sync(0xFFFFFFFFu, t1, 1));
            t1 = fmaxf(t1, __shfl_xor_sync(0xFFFFFFFFu, t1, 2));

            const float mn0 = fmaxf(m0, t0);
            const float mn1 = fmaxf(m1, t1);
            const float alpha0 = __expf(m0 - mn0);
            const float alpha1 = __expf(m1 - mn1);
            m0 = mn0; m1 = mn1;

            float sum0 = 0.0f, sum1 = 0.0f;
            const int pr0 = w * 16 + g;
            #pragma unroll
            for (int j = 0; j < 8; j++) {
                float p0 = __expf(s[j][0] - mn0);
                float p1 = __expf(s[j][1] - mn0);
                float p2 = __expf(s[j][2] - mn1);
                float p3 = __expf(s[j][3] - mn1);
                sum0 += p0 + p1;
                sum1 += p2 + p3;
                sP[pr0 * ALD + j * 8 + 2 * t]           = to_tf32(p0);
                sP[pr0 * ALD + j * 8 + 2 * t + 1]       = to_tf32(p1);
                sP[(pr0 + 8) * ALD + j * 8 + 2 * t]     = to_tf32(p2);
                sP[(pr0 + 8) * ALD + j * 8 + 2 * t + 1] = to_tf32(p3);
            }
            sum0 += __shfl_xor_sync(0xFFFFFFFFu, sum0, 1);
            sum0 += __shfl_xor_sync(0xFFFFFFFFu, sum0, 2);
            sum1 += __shfl_xor_sync(0xFFFFFFFFu, sum1, 1);
            sum1 += __shfl_xor_sync(0xFFFFFFFFu, sum1, 2);
            l0 = l0 * alpha0 + sum0;
            l1 = l1 * alpha1 + sum1;

            #pragma unroll
            for (int j = 0; j < 8; j++) {
                O[j][0] *= alpha0; O[j][1] *= alpha0;
                O[j][2] *= alpha1; O[j][3] *= alpha1;
            }
            __syncwarp();

            // ---- O += P @ V ----
            #pragma unroll
            for (int ks = 0; ks < 8; ks++) {
                uint32_t aP[4];
                aP[0] = __float_as_uint(sP[pr0 * ALD + ks * 8 + t]);
                aP[1] = __float_as_uint(sP[(pr0 + 8) * ALD + ks * 8 + t]);
                aP[2] = __float_as_uint(sP[pr0 * ALD + ks * 8 + t + 4]);
                aP[3] = __float_as_uint(sP[(pr0 + 8) * ALD + ks * 8 + t + 4]);
                #pragma unroll
                for (int j = 0; j < 8; j++) {
                    uint32_t b0 = __float_as_uint(sV[(ks * 8 + t) * ALD + j * 8 + g]);
                    uint32_t b1 = __float_as_uint(sV[(ks * 8 + t + 4) * ALD + j * 8 + g]);
                    mma_tf32_16x8x8(O[j], aP, b0, b1);
                }
            }
        }
    }

    // ---- Write y = tf32(O / l)  (feeds tf32 GEMM2 directly) ----
    {
        const float inv0 = 1.0f / l0;
        const float inv1 = 1.0f / l1;
        const int gr0 = q0 + w * 16 + g;
        float* y0 = y + ((size_t)b * TT + gr0) * EE + h * DD;
        float* y1 = y0 + 8 * EE;
        #pragma unroll
        for (int j = 0; j < 8; j++) {
            float2 v0 = { to_tf32(O[j][0] * inv0), to_tf32(O[j][1] * inv0) };
            float2 v1 = { to_tf32(O[j][2] * inv1), to_tf32(O[j][3] * inv1) };
            *(float2*)&y0[j * 8 + 2 * t] = v0;
            *(float2*)&y1[j * 8 + 2 * t] = v1;
        }
    }
}

// ---------------------------------------------------------------------------
// Launch
// ---------------------------------------------------------------------------
extern "C" void kernel_launch(void* const* d_in, const int* in_sizes, int n_in,
                              void* d_out, int out_size)
{
    const float* x      = (const float*)d_in[0];
    const float* W_qkv  = (const float*)d_in[1];
    const float* b_qkv  = (const float*)d_in[2];
    const float* W_proj = (const float*)d_in[3];
    const float* b_proj = (const float*)d_in[4];
    float* out = (float*)d_out;

    float *qkv, *y, *xc, *wq, *wp;
    cudaGetSymbolAddress((void**)&qkv, g_qkv);
    cudaGetSymbolAddress((void**)&y, g_y);
    cudaGetSymbolAddress((void**)&xc, g_xc);
    cudaGetSymbolAddress((void**)&wq, g_wq);
    cudaGetSymbolAddress((void**)&wp, g_wp);

    cudaFuncSetAttribute(gemm_tf32<true>,  cudaFuncAttributeMaxDynamicSharedMemorySize, GSMEM_BYTES);
    cudaFuncSetAttribute(gemm_tf32<false>, cudaFuncAttributeMaxDynamicSharedMemorySize, GSMEM_BYTES);
    cudaFuncSetAttribute(attn_tf32, cudaFuncAttributeMaxDynamicSharedMemorySize, ASMEM_BYTES);

    const int M = BATCH * TT;  // 8192

    // 0) tf32-round inputs
    {
        int n4x = (BATCH * TT * EE) / 4;      // 2097152
        int n4q = (EE * E3) / 4;              // 786432
        int n4p = (EE * EE) / 4;              // 262144
        cvt_tf32_kernel<<<(n4x + 255) / 256, 256>>>(x, xc, n4x);
        cvt_tf32_kernel<<<(n4q + 255) / 256, 256>>>(W_qkv, wq, n4q);
        cvt_tf32_kernel<<<(n4p + 255) / 256, 256>>>(W_proj, wp, n4p);
    }

    // 1) QKV projection (output rounded to tf32)
    {
        dim3 grid(E3 / 128, M / 128);
        gemm_tf32<true><<<grid, 256, GSMEM_BYTES>>>(xc, wq, b_qkv, qkv, M, E3, EE);
    }

    // 2) Attention
    {
        dim3 grid(TT / 128, BATCH * HH);
        attn_tf32<<<grid, 256, ASMEM_BYTES>>>(qkv, y);
    }

    // 3) Output projection (full fp32 output)
    {
        dim3 grid(EE / 128, M / 128);
        gemm_tf32<false><<<grid, 256, GSMEM_BYTES>>>(y, wp, b_proj, out, M, EE, EE);
    }
}

// round 5
// speedup vs baseline: 10.7122x; 2.7719x over previous
#include <cuda_runtime.h>
#include <cuda_fp16.h>
#include <mma.h>
#include <math.h>
#include <stdint.h>

using namespace nvcuda;

// Problem constants
#define BATCH 4
#define TT 2048
#define EE 1024
#define HH 16
#define DD 64
#define SEG 512
#define E3 3072

// Scratch (device globals: allocation-free)
static __device__ __half g_qkvh[(size_t)BATCH * TT * E3];  // [B,T,3E] half
static __device__ __half g_yh[(size_t)BATCH * TT * EE];    // [B,T,E] half
static __device__ __half g_xh[(size_t)BATCH * TT * EE];    // x half
static __device__ __half g_wqh[(size_t)EE * E3];           // W_qkv half
static __device__ __half g_wph[(size_t)EE * EE];           // W_proj half

// ---------------------------------------------------------------------------
// helpers
// ---------------------------------------------------------------------------
__device__ __forceinline__ void cp_async16(uint32_t smem_dst, const void* gsrc) {
    asm volatile("cp.async.cg.shared.global [%0], [%1], 16;\n" :: "r"(smem_dst), "l"(gsrc));
}
__device__ __forceinline__ void cp_commit() {
    asm volatile("cp.async.commit_group;\n" ::: "memory");
}
template <int N>
__device__ __forceinline__ void cp_wait() {
    asm volatile("cp.async.wait_group %0;\n" :: "n"(N) : "memory");
}

// fp32 -> fp16 conversion pre-pass (n4 float4 chunks)
__global__ __launch_bounds__(256) void cvt_f2h_kernel(
    const float* __restrict__ in, __half* __restrict__ out, int n4)
{
    int i = blockIdx.x * 256 + threadIdx.x;
    if (i < n4) {
        float4 v = ((const float4*)in)[i];
        __half2 h0 = __floats2half2_rn(v.x, v.y);
        __half2 h1 = __floats2half2_rn(v.z, v.w);
        ((__half2*)out)[i * 2]     = h0;
        ((__half2*)out)[i * 2 + 1] = h1;
    }
}

// ---------------------------------------------------------------------------
// FP16 GEMM: C[M,N] = A[M,K] @ B[K,N] + bias[N]   (A,B half; acc fp32)
// 128x128 block tile, BK=32, 2-stage cp.async, 256 threads (8 warps 4x2),
// warp tile 32x64, wmma m16n16k16 f16->f32.
// OutT = __half (qkv path) or float (final output).
// ---------------------------------------------------------------------------
#define GLDA 40
#define GLDB 136
#define A_H (128 * GLDA)             // 5120 halves
#define B_H (32 * GLDB)              // 4352 halves
#define STAGE_H (A_H + B_H)          // 9472 halves = 18944 B
#define GSMEM_BYTES (128 * 132 * 4)  // epilogue overlay dominates (67584 B)

template <typename OutT>
__global__ __launch_bounds__(256, 2) void gemm_f16(
    const __half* __restrict__ A, const __half* __restrict__ B,
    const float* __restrict__ bias, OutT* __restrict__ C,
    int M, int N, int K)
{
    extern __shared__ __half smemh[];
    const uint32_t smem_base = (uint32_t)__cvta_generic_to_shared(smemh);

    const int tid = threadIdx.x;
    const int wid = tid >> 5;
    const int wm = wid >> 1;
    const int wn = wid & 1;
    const int row0 = blockIdx.y * 128;
    const int col0 = blockIdx.x * 128;

    const int nsteps = K >> 5;   // K/32

    auto stage_load = [&](int s, int k0) {
        uint32_t sa = smem_base + (uint32_t)(s * STAGE_H) * 2u;
        uint32_t sb = sa + (uint32_t)A_H * 2u;
        // A tile 128x32 halves: 512 16B chunks
        #pragma unroll
        for (int i = 0; i < 2; i++) {
            int c = tid + i * 256;
            int r = c >> 2, c8 = c & 3;
            cp_async16(sa + (uint32_t)(r * GLDA + c8 * 8) * 2u,
                       &A[(size_t)(row0 + r) * K + k0 + c8 * 8]);
        }
        // B tile 32x128 halves: 512 16B chunks
        #pragma unroll
        for (int i = 0; i < 2; i++) {
            int c = tid + i * 256;
            int r = c >> 4, c8 = c & 15;
            cp_async16(sb + (uint32_t)(r * GLDB + c8 * 8) * 2u,
                       &B[(size_t)(k0 + r) * N + col0 + c8 * 8]);
        }
    };

    wmma::fragment<wmma::accumulator, 16, 16, 16, float> acc[2][4];
    #pragma unroll
    for (int i = 0; i < 2; i++)
        #pragma unroll
        for (int j = 0; j < 4; j++)
            wmma::fill_fragment(acc[i][j], 0.0f);

    stage_load(0, 0); cp_commit();
    stage_load(1, 32); cp_commit();

    for (int step = 0; step < nsteps; step++) {
        cp_wait<1>();
        __syncthreads();
        const int cur = step & 1;
        const __half* sA = smemh + cur * STAGE_H;
        const __half* sB = sA + A_H;

        #pragma unroll
        for (int ks = 0; ks < 2; ks++) {
            wmma::fragment<wmma::matrix_a, 16, 16, 16, __half, wmma::row_major> af[2];
            wmma::fragment<wmma::matrix_b, 16, 16, 16, __half, wmma::row_major> bf[4];
            #pragma unroll
            for (int i = 0; i < 2; i++)
                wmma::load_matrix_sync(af[i], &sA[(wm * 32 + 16 * i) * GLDA + ks * 16], GLDA);
            #pragma unroll
            for (int j = 0; j < 4; j++)
                wmma::load_matrix_sync(bf[j], &sB[(ks * 16) * GLDB + wn * 64 + 16 * j], GLDB);
            #pragma unroll
            for (int i = 0; i < 2; i++)
                #pragma unroll
                for (int j = 0; j < 4; j++)
                    wmma::mma_sync(acc[i][j], af[i], bf[j], acc[i][j]);
        }
        __syncthreads();
        if (step + 2 < nsteps) stage_load(cur, (step + 2) * 32);
        cp_commit();
    }

    // Epilogue via fp32 smem overlay
    float* sC = (float*)smemh;  // [128][132]
    __syncthreads();
    #pragma unroll
    for (int i = 0; i < 2; i++)
        #pragma unroll
        for (int j = 0; j < 4; j++)
            wmma::store_matrix_sync(&sC[(wm * 32 + 16 * i) * 132 + wn * 64 + 16 * j],
                                    acc[i][j], 132, wmma::mem_row_major);
    __syncthreads();

    #pragma unroll
    for (int idx = tid; idx < 4096; idx += 256) {
        int r = idx >> 5, c4 = idx & 31;
        float4 v = *(float4*)&sC[r * 132 + c4 * 4];
        float4 bv = *(const float4*)&bias[col0 + c4 * 4];
        v.x += bv.x; v.y += bv.y; v.z += bv.z; v.w += bv.w;
        if (sizeof(OutT) == 2) {
            __half2 h0 = __floats2half2_rn(v.x, v.y);
            __half2 h1 = __floats2half2_rn(v.z, v.w);
            __half2* dst = (__half2*)&C[(size_t)(row0 + r) * N + col0 + c4 * 4];
            dst[0] = h0; dst[1] = h1;
        } else {
            *(float4*)&((float*)C)[(size_t)(row0 + r) * N + col0 + c4 * 4] = v;
        }
    }
}

// ---------------------------------------------------------------------------
// Flash attention, mma.sync.m16n8k16.f16 (fp32 acc). Br=128, Bc=64, 8 warps.
// Q/K staged via cp.async; V stored TRANSPOSED in smem (sVt[d][key]) so
// P@V b-frags are contiguous half2. All smem leading dims 72 (conflict-free).
// ---------------------------------------------------------------------------
#define LDH 72
#define ASMEM_BYTES ((64 * LDH + 64 * LDH + 128 * LDH) * 2)   // 36864 B

__device__ __forceinline__ void mma_f16_16x8x16(
    float c[4], const uint32_t a[4], const uint32_t b0, const uint32_t b1)
{
    asm volatile(
        "mma.sync.aligned.m16n8k16.row.col.f32.f16.f16.f32 "
        "{%0,%1,%2,%3}, {%4,%5,%6,%7}, {%8,%9}, {%0,%1,%2,%3};"
        : "+f"(c[0]), "+f"(c[1]), "+f"(c[2]), "+f"(c[3])
        : "r"(a[0]), "r"(a[1]), "r"(a[2]), "r"(a[3]), "r"(b0), "r"(b1));
}

__global__ __launch_bounds__(256) void attn_f16(
    const __half* __restrict__ qkv, __half* __restrict__ y)
{
    extern __shared__ __half smemh[];
    __half* sK  = smemh;                   // [64][LDH]
    __half* sVt = smemh + 64 * LDH;        // [64 d][LDH keys]  (V transposed)
    __half* sP  = smemh + 128 * LDH;       // [128][LDH]  (Q staging, then P)
    const uint32_t smem_u = (uint32_t)__cvta_generic_to_shared(smemh);
    const uint32_t sK_u = smem_u;
    const uint32_t sP_u = smem_u + 128 * LDH * 2;

    const int tid = threadIdx.x;
    const int w = tid >> 5;
    const int lane = tid & 31;
    const int g = lane >> 2;
    const int t = lane & 3;

    const int q0 = blockIdx.x * 128;
    const int bh = blockIdx.y;
    const int b = bh / HH;
    const int h = bh % HH;

    const __half* base = qkv + (size_t)b * TT * E3 + h * DD;

    // ---- Stage Q tile (128x64 halves) via cp.async ----
    #pragma unroll
    for (int i = 0; i < 4; i++) {
        int idx = tid + i * 256;
        int r = idx >> 3, c8 = idx & 7;
        cp_async16(sP_u + (uint32_t)(r * LDH + c8 * 8) * 2u,
                   &base[(size_t)(q0 + r) * E3 + c8 * 8]);
    }
    cp_commit();
    cp_wait<0>();
    __syncthreads();

    // ---- Q a-frags (m16n8k16): 4 k-steps ----
    uint32_t aQ[4][4];
    {
        const int r0 = w * 16 + g;
        #pragma unroll
        for (int ks = 0; ks < 4; ks++) {
            aQ[ks][0] = *(const uint32_t*)&sP[r0 * LDH + ks * 16 + 2 * t];
            aQ[ks][1] = *(const uint32_t*)&sP[(r0 + 8) * LDH + ks * 16 + 2 * t];
            aQ[ks][2] = *(const uint32_t*)&sP[r0 * LDH + ks * 16 + 2 * t + 8];
            aQ[ks][3] = *(const uint32_t*)&sP[(r0 + 8) * LDH + ks * 16 + 2 * t + 8];
        }
    }

    float O[8][4];
    #pragma unroll
    for (int j = 0; j < 8; j++) { O[j][0] = O[j][1] = O[j][2] = O[j][3] = 0.0f; }
    float m0 = -1e30f, m1 = -1e30f, l0 = 0.0f, l1 = 0.0f;

    const bool causal = (q0 >= SEG);
    const int kv_end = causal ? (q0 + 128) : SEG;
    const int row0g = q0 + w * 16 + g;
    const int rowmax = q0 + w * 16 + 15;
    const float scale = 0.125f;

    for (int kc0 = 0; kc0 < kv_end; kc0 += 64) {
        __syncthreads();
        // ---- K via cp.async (64x64 halves) ----
        #pragma unroll
        for (int i = 0; i < 2; i++) {
            int idx = tid + i * 256;
            int r = idx >> 3, c8 = idx & 7;
            cp_async16(sK_u + (uint32_t)(r * LDH + c8 * 8) * 2u,
                       &base[(size_t)(kc0 + r) * E3 + EE + c8 * 8]);
        }
        cp_commit();
        // ---- V transposed into sVt: read half2, scatter halves ----
        #pragma unroll
        for (int i = 0; i < 8; i++) {
            int idx = tid + i * 256;
            int r = idx >> 5;              // key 0..63
            int c = (idx & 31) * 2;        // d 0..62
            __half2 v2 = *(const __half2*)&base[(size_t)(kc0 + r) * E3 + 2 * EE + c];
            sVt[c * LDH + r] = __low2half(v2);
            sVt[(c + 1) * LDH + r] = __high2half(v2);
        }
        cp_wait<0>();
        __syncthreads();

        const bool active = !(causal && kc0 > rowmax);
        if (active) {
            // ---- S = Q @ K^T ----
            float s[8][4];
            #pragma unroll
            for (int j = 0; j < 8; j++) {
                s[j][0] = s[j][1] = s[j][2] = s[j][3] = 0.0f;
                #pragma unroll
                for (int ks = 0; ks < 4; ks++) {
                    uint32_t b0 = *(const uint32_t*)&sK[(j * 8 + g) * LDH + ks * 16 + 2 * t];
                    uint32_t b1 = *(const uint32_t*)&sK[(j * 8 + g) * LDH + ks * 16 + 2 * t + 8];
                    mma_f16_16x8x16(s[j], aQ[ks], b0, b1);
                }
            }

            // ---- scale + mask + online softmax ----
            const bool maskT = causal && (kc0 + 63 > q0 + w * 16);
            float t0 = -1e30f, t1 = -1e30f;
            #pragma unroll
            for (int j = 0; j < 8; j++) {
                int c = kc0 + j * 8 + 2 * t;
                #pragma unroll
                for (int e = 0; e < 4; e++) {
                    float v = s[j][e] * scale;
                    int col = c + (e & 1);
                    int row = row0g + ((e >> 1) << 3);
                    if (maskT && col > row) v = -1e30f;
                    s[j][e] = v;
                }
                t0 = fmaxf(t0, fmaxf(s[j][0], s[j][1]));
                t1 = fmaxf(t1, fmaxf(s[j][2], s[j][3]));
            }
            t0 = fmaxf(t0, __shfl_xor_sync(0xFFFFFFFFu, t0, 1));
            t0 = fmaxf(t0, __shfl_xor_sync(0xFFFFFFFFu, t0, 2));
            t1 = fmaxf(t1, __shfl_xor_sync(0xFFFFFFFFu, t1, 1));
            t1 = fmaxf(t1, __shfl_xor_sync(0xFFFFFFFFu, t1, 2));

            const float mn0 = fmaxf(m0, t0);
            const float mn1 = fmaxf(m1, t1);
            const float alpha0 = __expf(m0 - mn0);
            const float alpha1 = __expf(m1 - mn1);
            m0 = mn0; m1 = mn1;

            float sum0 = 0.0f, sum1 = 0.0f;
            const int pr0 = w * 16 + g;
            #pragma unroll
            for (int j = 0; j < 8; j++) {
                float p0 = __expf(s[j][0] - mn0);
                float p1 = __expf(s[j][1] - mn0);
                float p2 = __expf(s[j][2] - mn1);
                float p3 = __expf(s[j][3] - mn1);
                sum0 += p0 + p1;
                sum1 += p2 + p3;
                *(__half2*)&sP[pr0 * LDH + j * 8 + 2 * t]       = __floats2half2_rn(p0, p1);
                *(__half2*)&sP[(pr0 + 8) * LDH + j * 8 + 2 * t] = __floats2half2_rn(p2, p3);
            }
            sum0 += __shfl_xor_sync(0xFFFFFFFFu, sum0, 1);
            sum0 += __shfl_xor_sync(0xFFFFFFFFu, sum0, 2);
            sum1 += __shfl_xor_sync(0xFFFFFFFFu, sum1, 1);
            sum1 += __shfl_xor_sync(0xFFFFFFFFu, sum1, 2);
            l0 = l0 * alpha0 + sum0;
            l1 = l1 * alpha1 + sum1;

            #pragma unroll
            for (int j = 0; j < 8; j++) {
                O[j][0] *= alpha0; O[j][1] *= alpha0;
                O[j][2] *= alpha1; O[j][3] *= alpha1;
            }
            __syncwarp();

            // ---- O += P @ V  (b-frags contiguous from sVt) ----
            #pragma unroll
            for (int ks = 0; ks < 4; ks++) {
                uint32_t aP[4];
                aP[0] = *(const uint32_t*)&sP[pr0 * LDH + ks * 16 + 2 * t];
                aP[1] = *(const uint32_t*)&sP[(pr0 + 8) * LDH + ks * 16 + 2 * t];
                aP[2] = *(const uint32_t*)&sP[pr0 * LDH + ks * 16 + 2 * t + 8];
                aP[3] = *(const uint32_t*)&sP[(pr0 + 8) * LDH + ks * 16 + 2 * t + 8];
                #pragma unroll
                for (int j = 0; j < 8; j++) {
                    uint32_t b0 = *(const uint32_t*)&sVt[(j * 8 + g) * LDH + ks * 16 + 2 * t];
                    uint32_t b1 = *(const uint32_t*)&sVt[(j * 8 + g) * LDH + ks * 16 + 2 * t + 8];
                    mma_f16_16x8x16(O[j], aP, b0, b1);
                }
            }
        }
    }

    // ---- Write y = half(O / l) ----
    {
        const float inv0 = 1.0f / l0;
        const float inv1 = 1.0f / l1;
        const int gr0 = q0 + w * 16 + g;
        __half* y0 = y + ((size_t)b * TT + gr0) * EE + h * DD;
        __half* y1 = y0 + 8 * EE;
        #pragma unroll
        for (int j = 0; j < 8; j++) {
            *(__half2*)&y0[j * 8 + 2 * t] = __floats2half2_rn(O[j][0] * inv0, O[j][1] * inv0);
            *(__half2*)&y1[j * 8 + 2 * t] = __floats2half2_rn(O[j][2] * inv1, O[j][3] * inv1);
        }
    }
}

// ---------------------------------------------------------------------------
// Launch
// ---------------------------------------------------------------------------
extern "C" void kernel_launch(void* const* d_in, const int* in_sizes, int n_in,
                              void* d_out, int out_size)
{
    const float* x      = (const float*)d_in[0];
    const float* W_qkv  = (const float*)d_in[1];
    const float* b_qkv  = (const float*)d_in[2];
    const float* W_proj = (const float*)d_in[3];
    const float* b_proj = (const float*)d_in[4];
    float* out = (float*)d_out;

    __half *qkvh, *yh, *xh, *wqh, *wph;
    cudaGetSymbolAddress((void**)&qkvh, g_qkvh);
    cudaGetSymbolAddress((void**)&yh, g_yh);
    cudaGetSymbolAddress((void**)&xh, g_xh);
    cudaGetSymbolAddress((void**)&wqh, g_wqh);
    cudaGetSymbolAddress((void**)&wph, g_wph);

    cudaFuncSetAttribute(gemm_f16<__half>, cudaFuncAttributeMaxDynamicSharedMemorySize, GSMEM_BYTES);
    cudaFuncSetAttribute(gemm_f16<float>,  cudaFuncAttributeMaxDynamicSharedMemorySize, GSMEM_BYTES);
    cudaFuncSetAttribute(attn_f16, cudaFuncAttributeMaxDynamicSharedMemorySize, ASMEM_BYTES);

    const int M = BATCH * TT;  // 8192

    // 0) fp32 -> fp16 conversion of inputs
    {
        int n4x = (BATCH * TT * EE) / 4;
        int n4q = (EE * E3) / 4;
        int n4p = (EE * EE) / 4;
        cvt_f2h_kernel<<<(n4x + 255) / 256, 256>>>(x, xh, n4x);
        cvt_f2h_kernel<<<(n4q + 255) / 256, 256>>>(W_qkv, wqh, n4q);
        cvt_f2h_kernel<<<(n4p + 255) / 256, 256>>>(W_proj, wph, n4p);
    }

    // 1) QKV projection (half output)
    {
        dim3 grid(E3 / 128, M / 128);
        gemm_f16<__half><<<grid, 256, GSMEM_BYTES>>>(xh, wqh, b_qkv, qkvh, M, E3, EE);
    }

    // 2) Attention (half output)
    {
        dim3 grid(TT / 128, BATCH * HH);
        attn_f16<<<grid, 256, ASMEM_BYTES>>>(qkvh, yh);
    }

    // 3) Output projection (fp32 output)
    {
        dim3 grid(EE / 128, M / 128);
        gemm_f16<float><<<grid, 256, GSMEM_BYTES>>>(yh, wph, b_proj, out, M, EE, EE);
    }
}

// round 6
// speedup vs baseline: 12.9662x; 1.2104x over previous
#include <cuda_runtime.h>
#include <cuda_fp16.h>
#include <mma.h>
#include <math.h>
#include <stdint.h>

using namespace nvcuda;

// Problem constants
#define BATCH 4
#define TT 2048
#define EE 1024
#define HH 16
#define DD 64
#define SEG 512
#define E3 3072

// Scratch (device globals: allocation-free)
static __device__ __half g_qkvh[(size_t)BATCH * TT * E3];
static __device__ __half g_yh[(size_t)BATCH * TT * EE];
static __device__ __half g_xh[(size_t)BATCH * TT * EE];
static __device__ __half g_wqh[(size_t)EE * E3];
static __device__ __half g_wph[(size_t)EE * EE];

// ---------------------------------------------------------------------------
// helpers
// ---------------------------------------------------------------------------
__device__ __forceinline__ void cp_async16(uint32_t smem_dst, const void* gsrc) {
    asm volatile("cp.async.cg.shared.global [%0], [%1], 16;\n" :: "r"(smem_dst), "l"(gsrc));
}
__device__ __forceinline__ void cp_commit() {
    asm volatile("cp.async.commit_group;\n" ::: "memory");
}
template <int N>
__device__ __forceinline__ void cp_wait() {
    asm volatile("cp.async.wait_group %0;\n" :: "n"(N) : "memory");
}
__device__ __forceinline__ void ldsm_x4_trans(
    uint32_t& r0, uint32_t& r1, uint32_t& r2, uint32_t& r3, uint32_t addr)
{
    asm volatile("ldmatrix.sync.aligned.m8n8.x4.trans.shared.b16 {%0,%1,%2,%3}, [%4];"
        : "=r"(r0), "=r"(r1), "=r"(r2), "=r"(r3) : "r"(addr));
}

// fp32 -> fp16 conversion pre-pass
__global__ __launch_bounds__(256) void cvt_f2h_kernel(
    const float* __restrict__ in, __half* __restrict__ out, int n4)
{
    int i = blockIdx.x * 256 + threadIdx.x;
    if (i < n4) {
        float4 v = ((const float4*)in)[i];
        ((__half2*)out)[i * 2]     = __floats2half2_rn(v.x, v.y);
        ((__half2*)out)[i * 2 + 1] = __floats2half2_rn(v.z, v.w);
    }
}

// ---------------------------------------------------------------------------
// FP16 GEMM: C[M,N] = A[M,K] @ B[K,N] + bias[N]; 128x128 tile, BK=32,
// 3-stage cp.async pipeline, 8 warps (4x2), warp tile 32x64, m16n16k16.
// ---------------------------------------------------------------------------
#define GLDA 40
#define GLDB 136
#define A_H (128 * GLDA)
#define B_H (32 * GLDB)
#define STAGE_H (A_H + B_H)          // 9472 halves
#define GSMEM_BYTES (128 * 132 * 4)  // epilogue overlay dominates; > 3*STAGE_H*2

template <typename OutT>
__global__ __launch_bounds__(256, 2) void gemm_f16(
    const __half* __restrict__ A, const __half* __restrict__ B,
    const float* __restrict__ bias, OutT* __restrict__ C,
    int M, int N, int K)
{
    extern __shared__ __half smemh[];
    const uint32_t smem_base = (uint32_t)__cvta_generic_to_shared(smemh);

    const int tid = threadIdx.x;
    const int wid = tid >> 5;
    const int wm = wid >> 1;
    const int wn = wid & 1;
    const int row0 = blockIdx.y * 128;
    const int col0 = blockIdx.x * 128;

    const int nsteps = K >> 5;

    auto stage_load = [&](int s, int k0) {
        uint32_t sa = smem_base + (uint32_t)(s * STAGE_H) * 2u;
        uint32_t sb = sa + (uint32_t)A_H * 2u;
        #pragma unroll
        for (int i = 0; i < 2; i++) {
            int c = tid + i * 256;
            int r = c >> 2, c8 = c & 3;
            cp_async16(sa + (uint32_t)(r * GLDA + c8 * 8) * 2u,
                       &A[(size_t)(row0 + r) * K + k0 + c8 * 8]);
        }
        #pragma unroll
        for (int i = 0; i < 2; i++) {
            int c = tid + i * 256;
            int r = c >> 4, c8 = c & 15;
            cp_async16(sb + (uint32_t)(r * GLDB + c8 * 8) * 2u,
                       &B[(size_t)(k0 + r) * N + col0 + c8 * 8]);
        }
    };

    wmma::fragment<wmma::accumulator, 16, 16, 16, float> acc[2][4];
    #pragma unroll
    for (int i = 0; i < 2; i++)
        #pragma unroll
        for (int j = 0; j < 4; j++)
            wmma::fill_fragment(acc[i][j], 0.0f);

    stage_load(0, 0); cp_commit();
    stage_load(1, 32); cp_commit();

    for (int step = 0; step < nsteps; step++) {
        // prefetch 2 ahead (buffer freed by step-1's trailing sync)
        if (step + 2 < nsteps) stage_load((step + 2) % 3, (step + 2) * 32);
        cp_commit();

        cp_wait<2>();
        __syncthreads();

        const __half* sA = smemh + (step % 3) * STAGE_H;
        const __half* sB = sA + A_H;

        #pragma unroll
        for (int ks = 0; ks < 2; ks++) {
            wmma::fragment<wmma::matrix_a, 16, 16, 16, __half, wmma::row_major> af[2];
            wmma::fragment<wmma::matrix_b, 16, 16, 16, __half, wmma::row_major> bf[4];
            #pragma unroll
            for (int i = 0; i < 2; i++)
                wmma::load_matrix_sync(af[i], &sA[(wm * 32 + 16 * i) * GLDA + ks * 16], GLDA);
            #pragma unroll
            for (int j = 0; j < 4; j++)
                wmma::load_matrix_sync(bf[j], &sB[(ks * 16) * GLDB + wn * 64 + 16 * j], GLDB);
            #pragma unroll
            for (int i = 0; i < 2; i++)
                #pragma unroll
                for (int j = 0; j < 4; j++)
                    wmma::mma_sync(acc[i][j], af[i], bf[j], acc[i][j]);
        }
        __syncthreads();
    }

    // Epilogue via fp32 smem overlay
    float* sC = (float*)smemh;
    #pragma unroll
    for (int i = 0; i < 2; i++)
        #pragma unroll
        for (int j = 0; j < 4; j++)
            wmma::store_matrix_sync(&sC[(wm * 32 + 16 * i) * 132 + wn * 64 + 16 * j],
                                    acc[i][j], 132, wmma::mem_row_major);
    __syncthreads();

    #pragma unroll
    for (int idx = tid; idx < 4096; idx += 256) {
        int r = idx >> 5, c4 = idx & 31;
        float4 v = *(float4*)&sC[r * 132 + c4 * 4];
        float4 bv = *(const float4*)&bias[col0 + c4 * 4];
        v.x += bv.x; v.y += bv.y; v.z += bv.z; v.w += bv.w;
        if (sizeof(OutT) == 2) {
            __half2* dst = (__half2*)&C[(size_t)(row0 + r) * N + col0 + c4 * 4];
            dst[0] = __floats2half2_rn(v.x, v.y);
            dst[1] = __floats2half2_rn(v.z, v.w);
        } else {
            *(float4*)&((float*)C)[(size_t)(row0 + r) * N + col0 + c4 * 4] = v;
        }
    }
}

// ---------------------------------------------------------------------------
// Flash attention, m16n8k16.f16 (fp32 acc). Br=128, Bc=64, 8 warps.
// Double-buffered K/V tiles via cp.async (1 tile ahead). V kept row-major;
// V^T b-frags produced by ldmatrix.x4.trans. LDH=72 (conflict-free).
// ---------------------------------------------------------------------------
#define LDH 72
#define KV_TILE (64 * LDH)   // halves
#define ASMEM_BYTES ((4 * KV_TILE + 128 * LDH) * 2)   // 55296 B

__device__ __forceinline__ void mma_f16_16x8x16(
    float c[4], const uint32_t a[4], const uint32_t b0, const uint32_t b1)
{
    asm volatile(
        "mma.sync.aligned.m16n8k16.row.col.f32.f16.f16.f32 "
        "{%0,%1,%2,%3}, {%4,%5,%6,%7}, {%8,%9}, {%0,%1,%2,%3};"
        : "+f"(c[0]), "+f"(c[1]), "+f"(c[2]), "+f"(c[3])
        : "r"(a[0]), "r"(a[1]), "r"(a[2]), "r"(a[3]), "r"(b0), "r"(b1));
}

__global__ __launch_bounds__(256) void attn_f16(
    const __half* __restrict__ qkv, __half* __restrict__ y)
{
    extern __shared__ __half smemh[];
    // layout: sK[0], sK[1], sV[0], sV[1], sP
    __half* sP = smemh + 4 * KV_TILE;
    const uint32_t smem_u = (uint32_t)__cvta_generic_to_shared(smemh);
    const uint32_t sP_u = smem_u + (uint32_t)(4 * KV_TILE) * 2u;

    const int tid = threadIdx.x;
    const int w = tid >> 5;
    const int lane = tid & 31;
    const int g = lane >> 2;
    const int t = lane & 3;

    const int q0 = blockIdx.x * 128;
    const int bh = blockIdx.y;
    const int b = bh / HH;
    const int h = bh % HH;

    const __half* base = qkv + (size_t)b * TT * E3 + h * DD;

    const bool causal = (q0 >= SEG);
    const int kv_end = causal ? (q0 + 128) : SEG;
    const int ntiles = kv_end >> 6;

    auto prefetch = [&](int tile, int s) {
        uint32_t k_u = smem_u + (uint32_t)(s * KV_TILE) * 2u;
        uint32_t v_u = smem_u + (uint32_t)((2 + s) * KV_TILE) * 2u;
        const int kc0 = tile * 64;
        #pragma unroll
        for (int i = 0; i < 2; i++) {
            int idx = tid + i * 256;
            int r = idx >> 3, c8 = idx & 7;
            const __half* gp = &base[(size_t)(kc0 + r) * E3 + c8 * 8];
            uint32_t soff = (uint32_t)(r * LDH + c8 * 8) * 2u;
            cp_async16(k_u + soff, gp + EE);
            cp_async16(v_u + soff, gp + 2 * EE);
        }
    };

    // ---- Q staging (group 0) + tile0 prefetch (group 1) ----
    #pragma unroll
    for (int i = 0; i < 4; i++) {
        int idx = tid + i * 256;
        int r = idx >> 3, c8 = idx & 7;
        cp_async16(sP_u + (uint32_t)(r * LDH + c8 * 8) * 2u,
                   &base[(size_t)(q0 + r) * E3 + c8 * 8]);
    }
    cp_commit();
    prefetch(0, 0);
    cp_commit();

    cp_wait<1>();       // Q done
    __syncthreads();

    // ---- Q a-frags ----
    uint32_t aQ[4][4];
    {
        const int r0 = w * 16 + g;
        #pragma unroll
        for (int ks = 0; ks < 4; ks++) {
            aQ[ks][0] = *(const uint32_t*)&sP[r0 * LDH + ks * 16 + 2 * t];
            aQ[ks][1] = *(const uint32_t*)&sP[(r0 + 8) * LDH + ks * 16 + 2 * t];
            aQ[ks][2] = *(const uint32_t*)&sP[r0 * LDH + ks * 16 + 2 * t + 8];
            aQ[ks][3] = *(const uint32_t*)&sP[(r0 + 8) * LDH + ks * 16 + 2 * t + 8];
        }
    }
    __syncthreads();    // sP free for P usage

    float O[8][4];
    #pragma unroll
    for (int j = 0; j < 8; j++) { O[j][0] = O[j][1] = O[j][2] = O[j][3] = 0.0f; }
    float m0 = -1e30f, m1 = -1e30f, l0 = 0.0f, l1 = 0.0f;

    const int row0g = q0 + w * 16 + g;
    const int rowmax = q0 + w * 16 + 15;
    const float scale = 0.125f;

    for (int tile = 0; tile < ntiles; tile++) {
        const int s = tile & 1;
        const int kc0 = tile * 64;

        if (tile + 1 < ntiles) prefetch(tile + 1, s ^ 1);
        cp_commit();
        cp_wait<1>();        // tile's group done (next tile's may be in flight)
        __syncthreads();

        const __half* sK = smemh + s * KV_TILE;
        const uint32_t sV_u = smem_u + (uint32_t)((2 + s) * KV_TILE) * 2u;

        const bool active = !(causal && kc0 > rowmax);
        if (active) {
            // ---- S = Q @ K^T ----
            float sacc[8][4];
            #pragma unroll
            for (int j = 0; j < 8; j++) {
                sacc[j][0] = sacc[j][1] = sacc[j][2] = sacc[j][3] = 0.0f;
                #pragma unroll
                for (int ks = 0; ks < 4; ks++) {
                    uint32_t b0 = *(const uint32_t*)&sK[(j * 8 + g) * LDH + ks * 16 + 2 * t];
                    uint32_t b1 = *(const uint32_t*)&sK[(j * 8 + g) * LDH + ks * 16 + 2 * t + 8];
                    mma_f16_16x8x16(sacc[j], aQ[ks], b0, b1);
                }
            }

            // ---- scale + mask + online softmax ----
            const bool maskT = causal && (kc0 + 63 > q0 + w * 16);
            float t0 = -1e30f, t1 = -1e30f;
            #pragma unroll
            for (int j = 0; j < 8; j++) {
                int c = kc0 + j * 8 + 2 * t;
                #pragma unroll
                for (int e = 0; e < 4; e++) {
                    float v = sacc[j][e] * scale;
                    int col = c + (e & 1);
                    int row = row0g + ((e >> 1) << 3);
                    if (maskT && col > row) v = -1e30f;
                    sacc[j][e] = v;
                }
                t0 = fmaxf(t0, fmaxf(sacc[j][0], sacc[j][1]));
                t1 = fmaxf(t1, fmaxf(sacc[j][2], sacc[j][3]));
            }
            t0 = fmaxf(t0, __shfl_xor_sync(0xFFFFFFFFu, t0, 1));
            t0 = fmaxf(t0, __shfl_xor_sync(0xFFFFFFFFu, t0, 2));
            t1 = fmaxf(t1, __shfl_xor_sync(0xFFFFFFFFu, t1, 1));
            t1 = fmaxf(t1, __shfl_xor_sync(0xFFFFFFFFu, t1, 2));

            const float mn0 = fmaxf(m0, t0);
            const float mn1 = fmaxf(m1, t1);
            const float alpha0 = __expf(m0 - mn0);
            const float alpha1 = __expf(m1 - mn1);
            m0 = mn0; m1 = mn1;

            float sum0 = 0.0f, sum1 = 0.0f;
            const int pr0 = w * 16 + g;
            #pragma unroll
            for (int j = 0; j < 8; j++) {
                float p0 = __expf(sacc[j][0] - mn0);
                float p1 = __expf(sacc[j][1] - mn0);
                float p2 = __expf(sacc[j][2] - mn1);
                float p3 = __expf(sacc[j][3] - mn1);
                sum0 += p0 + p1;
                sum1 += p2 + p3;
                *(__half2*)&sP[pr0 * LDH + j * 8 + 2 * t]       = __floats2half2_rn(p0, p1);
                *(__half2*)&sP[(pr0 + 8) * LDH + j * 8 + 2 * t] = __floats2half2_rn(p2, p3);
            }
            sum0 += __shfl_xor_sync(0xFFFFFFFFu, sum0, 1);
            sum0 += __shfl_xor_sync(0xFFFFFFFFu, sum0, 2);
            sum1 += __shfl_xor_sync(0xFFFFFFFFu, sum1, 1);
            sum1 += __shfl_xor_sync(0xFFFFFFFFu, sum1, 2);
            l0 = l0 * alpha0 + sum0;
            l1 = l1 * alpha1 + sum1;

            #pragma unroll
            for (int j = 0; j < 8; j++) {
                O[j][0] *= alpha0; O[j][1] *= alpha0;
                O[j][2] *= alpha1; O[j][3] *= alpha1;
            }
            __syncwarp();

            // ---- O += P @ V : V^T frags via ldmatrix.x4.trans ----
            #pragma unroll
            for (int ks = 0; ks < 4; ks++) {
                uint32_t aP[4];
                aP[0] = *(const uint32_t*)&sP[pr0 * LDH + ks * 16 + 2 * t];
                aP[1] = *(const uint32_t*)&sP[(pr0 + 8) * LDH + ks * 16 + 2 * t];
                aP[2] = *(const uint32_t*)&sP[pr0 * LDH + ks * 16 + 2 * t + 8];
                aP[3] = *(const uint32_t*)&sP[(pr0 + 8) * LDH + ks * 16 + 2 * t + 8];
                #pragma unroll
                for (int jj = 0; jj < 4; jj++) {
                    uint32_t r0, r1, r2, r3;
                    uint32_t addr = sV_u +
                        (uint32_t)(((ks * 16 + (lane & 15)) * LDH) + jj * 16 + ((lane >> 4) << 3)) * 2u;
                    ldsm_x4_trans(r0, r1, r2, r3, addr);
                    mma_f16_16x8x16(O[2 * jj],     aP, r0, r1);
                    mma_f16_16x8x16(O[2 * jj + 1], aP, r2, r3);
                }
            }
        }
        __syncthreads();   // all warps done with buffers before next prefetch overwrites
    }

    // ---- Write y = half(O / l) ----
    {
        const float inv0 = 1.0f / l0;
        const float inv1 = 1.0f / l1;
        const int gr0 = q0 + w * 16 + g;
        __half* y0 = y + ((size_t)b * TT + gr0) * EE + h * DD;
        __half* y1 = y0 + 8 * EE;
        #pragma unroll
        for (int j = 0; j < 8; j++) {
            *(__half2*)&y0[j * 8 + 2 * t] = __floats2half2_rn(O[j][0] * inv0, O[j][1] * inv0);
            *(__half2*)&y1[j * 8 + 2 * t] = __floats2half2_rn(O[j][2] * inv1, O[j][3] * inv1);
        }
    }
}

// ---------------------------------------------------------------------------
// Launch
// ---------------------------------------------------------------------------
extern "C" void kernel_launch(void* const* d_in, const int* in_sizes, int n_in,
                              void* d_out, int out_size)
{
    const float* x      = (const float*)d_in[0];
    const float* W_qkv  = (const float*)d_in[1];
    const float* b_qkv  = (const float*)d_in[2];
    const float* W_proj = (const float*)d_in[3];
    const float* b_proj = (const float*)d_in[4];
    float* out = (float*)d_out;

    __half *qkvh, *yh, *xh, *wqh, *wph;
    cudaGetSymbolAddress((void**)&qkvh, g_qkvh);
    cudaGetSymbolAddress((void**)&yh, g_yh);
    cudaGetSymbolAddress((void**)&xh, g_xh);
    cudaGetSymbolAddress((void**)&wqh, g_wqh);
    cudaGetSymbolAddress((void**)&wph, g_wph);

    cudaFuncSetAttribute(gemm_f16<__half>, cudaFuncAttributeMaxDynamicSharedMemorySize, GSMEM_BYTES);
    cudaFuncSetAttribute(gemm_f16<float>,  cudaFuncAttributeMaxDynamicSharedMemorySize, GSMEM_BYTES);
    cudaFuncSetAttribute(attn_f16, cudaFuncAttributeMaxDynamicSharedMemorySize, ASMEM_BYTES);

    const int M = BATCH * TT;  // 8192

    // 0) fp32 -> fp16 conversions
    {
        int n4x = (BATCH * TT * EE) / 4;
        int n4q = (EE * E3) / 4;
        int n4p = (EE * EE) / 4;
        cvt_f2h_kernel<<<(n4x + 255) / 256, 256>>>(x, xh, n4x);
        cvt_f2h_kernel<<<(n4q + 255) / 256, 256>>>(W_qkv, wqh, n4q);
        cvt_f2h_kernel<<<(n4p + 255) / 256, 256>>>(W_proj, wph, n4p);
    }

    // 1) QKV projection (half output)
    {
        dim3 grid(E3 / 128, M / 128);
        gemm_f16<__half><<<grid, 256, GSMEM_BYTES>>>(xh, wqh, b_qkv, qkvh, M, E3, EE);
    }

    // 2) Attention (half output)
    {
        dim3 grid(TT / 128, BATCH * HH);
        attn_f16<<<grid, 256, ASMEM_BYTES>>>(qkvh, yh);
    }

    // 3) Output projection (fp32 output)
    {
        dim3 grid(EE / 128, M / 128);
        gemm_f16<float><<<grid, 256, GSMEM_BYTES>>>(yh, wph, b_proj, out, M, EE, EE);
    }
}